// round 4
// baseline (speedup 1.0000x reference)
#include <cuda_runtime.h>
#include <math.h>

// ---------------------------------------------------------------------------
// MultiHeadSelfAttention: x(4,512,48,48) -> QKV proj -> 8-head attention
// (flash-style, online softmax) -> out proj.
// All fp32. Three kernels:
//   1) qkv_gemm : per-batch 1536x512 @ 512x2304 + bias, scattered to Q/K/V
//                 scratch in [b,h,d,s] layout; Q pre-scaled by d^-0.5.
//   2) flash_attn: 128-query x 128-key tiles, D=64, P through shared (aliased
//                  onto the K buffer), O accumulated in registers.
//   3) out_gemm : per-batch 512x512 @ 512x2304 + bias -> d_out.
// ---------------------------------------------------------------------------

#define BATCH 4
#define CDIM  512
#define SEQ   2304
#define NH    8
#define HD    64
#define MQKV  1536

#define SCRATCH_ELEMS (BATCH * CDIM * SEQ)   // 4,718,592 floats each (18 MB)

__device__ float g_Q[SCRATCH_ELEMS];
__device__ float g_K[SCRATCH_ELEMS];
__device__ float g_V[SCRATCH_ELEMS];
__device__ float g_O[SCRATCH_ELEMS];

// ---------------------------------------------------------------------------
// Kernel 1: QKV projection.
//   qkv[b,o,s] = sum_c Wqkv[o,c] * x[b,c,s] + bqkv[o]
// Tiling: BM=128, BN=128, BK=8, 256 threads, 8x8 per thread.
// Epilogue routes o -> (which, h, d) and writes [b,h,d,s]; Q scaled by 0.125.
// ---------------------------------------------------------------------------
__global__ __launch_bounds__(256) void qkv_gemm(
    const float* __restrict__ W,     // [1536, 512]
    const float* __restrict__ X,     // [B, 512, 2304]
    const float* __restrict__ bias)  // [1536]
{
    __shared__ float As[8][128];
    __shared__ float Bs[8][128];

    const int tid = threadIdx.x;
    const int b   = blockIdx.z;
    const int m0  = blockIdx.y * 128;
    const int n0  = blockIdx.x * 128;
    const float* Xb = X + (size_t)b * CDIM * SEQ;

    const int ar = tid >> 1;          // 0..127
    const int ac = (tid & 1) * 4;     // 0 or 4
    const int br = tid >> 5;          // 0..7
    const int bc = (tid & 31) * 4;    // 0..124
    const int ty = tid >> 4;          // 0..15
    const int tx = tid & 15;          // 0..15

    float acc[8][8];
#pragma unroll
    for (int i = 0; i < 8; i++)
#pragma unroll
        for (int j = 0; j < 8; j++) acc[i][j] = 0.0f;

    for (int k0 = 0; k0 < CDIM; k0 += 8) {
        float4 av = *(const float4*)(W  + (size_t)(m0 + ar) * CDIM + k0 + ac);
        float4 bv = *(const float4*)(Xb + (size_t)(k0 + br) * SEQ  + n0 + bc);
        __syncthreads();
        As[ac + 0][ar] = av.x; As[ac + 1][ar] = av.y;
        As[ac + 2][ar] = av.z; As[ac + 3][ar] = av.w;
        *(float4*)&Bs[br][bc] = bv;
        __syncthreads();
#pragma unroll
        for (int kk = 0; kk < 8; kk++) {
            float a[8], bb[8];
            *(float4*)&a[0]  = *(const float4*)&As[kk][ty * 8];
            *(float4*)&a[4]  = *(const float4*)&As[kk][ty * 8 + 4];
            *(float4*)&bb[0] = *(const float4*)&Bs[kk][tx * 8];
            *(float4*)&bb[4] = *(const float4*)&Bs[kk][tx * 8 + 4];
#pragma unroll
            for (int i = 0; i < 8; i++)
#pragma unroll
                for (int j = 0; j < 8; j++)
                    acc[i][j] += a[i] * bb[j];
        }
    }

    // Route: which = o/512 (q,k,v), rem = o%512 -> (h = rem/64, d = rem%64).
    // A whole 128-row tile lies in a single "which".
    const int which = m0 >> 9;
    float* dst = (which == 0) ? g_Q : (which == 1) ? g_K : g_V;
    const float qs = (which == 0) ? 0.125f : 1.0f;   // HEAD_DIM^-0.5 folded into Q

#pragma unroll
    for (int i = 0; i < 8; i++) {
        const int m   = m0 + ty * 8 + i;
        const int rem = m & 511;
        const float bv = bias[m];
        float* row = dst + (size_t)(b * CDIM + rem) * SEQ + n0 + tx * 8;
        float4 v0 = make_float4((acc[i][0] + bv) * qs, (acc[i][1] + bv) * qs,
                                (acc[i][2] + bv) * qs, (acc[i][3] + bv) * qs);
        float4 v1 = make_float4((acc[i][4] + bv) * qs, (acc[i][5] + bv) * qs,
                                (acc[i][6] + bv) * qs, (acc[i][7] + bv) * qs);
        *(float4*)row       = v0;
        *(float4*)(row + 4) = v1;
    }
}

// ---------------------------------------------------------------------------
// Kernel 2: flash attention. grid = (SEQ/128, B*NH), 256 threads.
// Shared (dynamic): Qs[64][128] | KP union( Ks[64][128], Ps[128][132] )
//                 | Vs[128][65] (V transposed) | cs[128] | ls[128]
// Score phase: thread(ty,tx) owns score rows sq=ty*8+i, cols t=tx*8+j (8x8).
// O phase:     thread(ty,tx) owns O rows d=ty*4+i, cols sq=tx*8+j (4x8).
// Softmax stats move between the two mappings through cs[]/ls[] in shared.
// ---------------------------------------------------------------------------
#define FLASH_SMEM_FLOATS (8192 + 16896 + 8320 + 256)
#define FLASH_SMEM_BYTES  (FLASH_SMEM_FLOATS * 4)

__global__ __launch_bounds__(256) void flash_attn()
{
    extern __shared__ float sm[];
    float* Qs = sm;                       // [d][sq], stride 128
    float* KP = sm + 8192;                // Ks [d][t] stride 128 / Ps [t][sq] stride 132
    float* Vs = KP + 16896;               // [t][d], stride 65 (conflict-free transpose)
    float* cs = Vs + 8320;                // [128] per-row correction (this tile)
    float* ls = cs + 128;                 // [128] final row sums

    const int tid = threadIdx.x;
    const int bh  = blockIdx.y;           // b*NH + h
    const int s0  = blockIdx.x * 128;
    const float* Qg = g_Q + (size_t)bh * HD * SEQ;
    const float* Kg = g_K + (size_t)bh * HD * SEQ;
    const float* Vg = g_V + (size_t)bh * HD * SEQ;
    float*       Og = g_O + (size_t)bh * HD * SEQ;

    const int ty = tid >> 4;              // 0..15
    const int tx = tid & 15;              // 0..15

    // Load Q tile once (coalesced in sq).
    for (int idx = tid; idx < 8192; idx += 256) {
        const int d  = idx >> 7;
        const int sq = idx & 127;
        Qs[idx] = Qg[(size_t)d * SEQ + s0 + sq];
    }

    float o_acc[4][8];
#pragma unroll
    for (int i = 0; i < 4; i++)
#pragma unroll
        for (int j = 0; j < 8; j++) o_acc[i][j] = 0.0f;

    float m_run[8], l_run[8];
#pragma unroll
    for (int i = 0; i < 8; i++) { m_run[i] = -1e30f; l_run[i] = 0.0f; }

    for (int t0 = 0; t0 < SEQ; t0 += 128) {
        __syncthreads();   // previous O-GEMM done reading KP/Vs (and Q load on iter 0)

        // Load K tile [d][t] and V tile transposed [t][d].
        for (int idx = tid; idx < 8192; idx += 256) {
            const int d = idx >> 7;
            const int t = idx & 127;
            KP[idx]         = Kg[(size_t)d * SEQ + t0 + t];
            Vs[t * 65 + d]  = Vg[(size_t)d * SEQ + t0 + t];
        }
        __syncthreads();

        // Score GEMM: s[sq][t] = sum_d Qs[d][sq] * Ks[d][t] (Q pre-scaled).
        float s_acc[8][8];
#pragma unroll
        for (int i = 0; i < 8; i++)
#pragma unroll
            for (int j = 0; j < 8; j++) s_acc[i][j] = 0.0f;

#pragma unroll 8
        for (int k = 0; k < 64; k++) {
            float a[8], bb[8];
            *(float4*)&a[0]  = *(const float4*)&Qs[k * 128 + ty * 8];
            *(float4*)&a[4]  = *(const float4*)&Qs[k * 128 + ty * 8 + 4];
            *(float4*)&bb[0] = *(const float4*)&KP[k * 128 + tx * 8];
            *(float4*)&bb[4] = *(const float4*)&KP[k * 128 + tx * 8 + 4];
#pragma unroll
            for (int i = 0; i < 8; i++)
#pragma unroll
                for (int j = 0; j < 8; j++)
                    s_acc[i][j] += a[i] * bb[j];
        }

        // Online softmax. Row group = 16 lanes sharing ty (contiguous half-warp).
#pragma unroll
        for (int i = 0; i < 8; i++) {
            float mx = s_acc[i][0];
#pragma unroll
            for (int j = 1; j < 8; j++) mx = fmaxf(mx, s_acc[i][j]);
            mx = fmaxf(mx, __shfl_xor_sync(0xffffffffu, mx, 8));
            mx = fmaxf(mx, __shfl_xor_sync(0xffffffffu, mx, 4));
            mx = fmaxf(mx, __shfl_xor_sync(0xffffffffu, mx, 2));
            mx = fmaxf(mx, __shfl_xor_sync(0xffffffffu, mx, 1));

            const float m_new = fmaxf(m_run[i], mx);
            const float c     = __expf(m_run[i] - m_new);   // 0 on first tile
            float rs = 0.0f;
#pragma unroll
            for (int j = 0; j < 8; j++) {
                s_acc[i][j] = __expf(s_acc[i][j] - m_new);  // P in place
                rs += s_acc[i][j];
            }
            rs += __shfl_xor_sync(0xffffffffu, rs, 8);
            rs += __shfl_xor_sync(0xffffffffu, rs, 4);
            rs += __shfl_xor_sync(0xffffffffu, rs, 2);
            rs += __shfl_xor_sync(0xffffffffu, rs, 1);

            l_run[i] = l_run[i] * c + rs;
            m_run[i] = m_new;
            if (tx == 0) cs[ty * 8 + i] = c;
        }
        __syncthreads();   // all K reads done; cs visible

        // Rescale O accumulator by this tile's correction (cols are sq=tx*8+j).
#pragma unroll
        for (int j = 0; j < 8; j++) {
            const float c = cs[tx * 8 + j];
#pragma unroll
            for (int i = 0; i < 4; i++) o_acc[i][j] *= c;
        }

        // Write P transposed into the K buffer: Ps[t][sq], stride 132.
#pragma unroll
        for (int j = 0; j < 8; j++) {
            float4 v0 = make_float4(s_acc[0][j], s_acc[1][j], s_acc[2][j], s_acc[3][j]);
            float4 v1 = make_float4(s_acc[4][j], s_acc[5][j], s_acc[6][j], s_acc[7][j]);
            float* prow = &KP[(tx * 8 + j) * 132 + ty * 8];
            *(float4*)prow       = v0;
            *(float4*)(prow + 4) = v1;
        }
        __syncthreads();

        // O GEMM: O[d][sq] += sum_t V[t][d] * P[t][sq].
#pragma unroll 4
        for (int t = 0; t < 128; t++) {
            const float a0 = Vs[t * 65 + ty * 4 + 0];
            const float a1 = Vs[t * 65 + ty * 4 + 1];
            const float a2 = Vs[t * 65 + ty * 4 + 2];
            const float a3 = Vs[t * 65 + ty * 4 + 3];
            float bb[8];
            *(float4*)&bb[0] = *(const float4*)&KP[t * 132 + tx * 8];
            *(float4*)&bb[4] = *(const float4*)&KP[t * 132 + tx * 8 + 4];
#pragma unroll
            for (int j = 0; j < 8; j++) {
                o_acc[0][j] += a0 * bb[j];
                o_acc[1][j] += a1 * bb[j];
                o_acc[2][j] += a2 * bb[j];
                o_acc[3][j] += a3 * bb[j];
            }
        }
    }

    // Publish final row sums, normalize, write O[b,h,d,s].
    if (tx == 0) {
#pragma unroll
        for (int i = 0; i < 8; i++) ls[ty * 8 + i] = l_run[i];
    }
    __syncthreads();

    float inv[8];
#pragma unroll
    for (int j = 0; j < 8; j++) inv[j] = 1.0f / ls[tx * 8 + j];

#pragma unroll
    for (int i = 0; i < 4; i++) {
        float* row = Og + (size_t)(ty * 4 + i) * SEQ + s0 + tx * 8;
        float4 v0 = make_float4(o_acc[i][0] * inv[0], o_acc[i][1] * inv[1],
                                o_acc[i][2] * inv[2], o_acc[i][3] * inv[3]);
        float4 v1 = make_float4(o_acc[i][4] * inv[4], o_acc[i][5] * inv[5],
                                o_acc[i][6] * inv[6], o_acc[i][7] * inv[7]);
        *(float4*)row       = v0;
        *(float4*)(row + 4) = v1;
    }
}

// ---------------------------------------------------------------------------
// Kernel 3: output projection.
//   out[b,o,s] = sum_c Wout[o,c] * g_O[b,c,s] + bout[o]
// ---------------------------------------------------------------------------
__global__ __launch_bounds__(256) void out_gemm(
    const float* __restrict__ W,     // [512, 512]
    const float* __restrict__ bias,  // [512]
    float* __restrict__ Y)           // [B, 512, 2304]
{
    __shared__ float As[8][128];
    __shared__ float Bs[8][128];

    const int tid = threadIdx.x;
    const int b   = blockIdx.z;
    const int m0  = blockIdx.y * 128;
    const int n0  = blockIdx.x * 128;
    const float* Xb = g_O + (size_t)b * CDIM * SEQ;

    const int ar = tid >> 1;
    const int ac = (tid & 1) * 4;
    const int br = tid >> 5;
    const int bc = (tid & 31) * 4;
    const int ty = tid >> 4;
    const int tx = tid & 15;

    float acc[8][8];
#pragma unroll
    for (int i = 0; i < 8; i++)
#pragma unroll
        for (int j = 0; j < 8; j++) acc[i][j] = 0.0f;

    for (int k0 = 0; k0 < CDIM; k0 += 8) {
        float4 av = *(const float4*)(W  + (size_t)(m0 + ar) * CDIM + k0 + ac);
        float4 bv = *(const float4*)(Xb + (size_t)(k0 + br) * SEQ  + n0 + bc);
        __syncthreads();
        As[ac + 0][ar] = av.x; As[ac + 1][ar] = av.y;
        As[ac + 2][ar] = av.z; As[ac + 3][ar] = av.w;
        *(float4*)&Bs[br][bc] = bv;
        __syncthreads();
#pragma unroll
        for (int kk = 0; kk < 8; kk++) {
            float a[8], bb[8];
            *(float4*)&a[0]  = *(const float4*)&As[kk][ty * 8];
            *(float4*)&a[4]  = *(const float4*)&As[kk][ty * 8 + 4];
            *(float4*)&bb[0] = *(const float4*)&Bs[kk][tx * 8];
            *(float4*)&bb[4] = *(const float4*)&Bs[kk][tx * 8 + 4];
#pragma unroll
            for (int i = 0; i < 8; i++)
#pragma unroll
                for (int j = 0; j < 8; j++)
                    acc[i][j] += a[i] * bb[j];
        }
    }

#pragma unroll
    for (int i = 0; i < 8; i++) {
        const int m = m0 + ty * 8 + i;
        const float bv = bias[m];
        float* row = Y + (size_t)(b * CDIM + m) * SEQ + n0 + tx * 8;
        float4 v0 = make_float4(acc[i][0] + bv, acc[i][1] + bv,
                                acc[i][2] + bv, acc[i][3] + bv);
        float4 v1 = make_float4(acc[i][4] + bv, acc[i][5] + bv,
                                acc[i][6] + bv, acc[i][7] + bv);
        *(float4*)row       = v0;
        *(float4*)(row + 4) = v1;
    }
}

// ---------------------------------------------------------------------------
extern "C" void kernel_launch(void* const* d_in, const int* in_sizes, int n_in,
                              void* d_out, int out_size)
{
    const float* x    = (const float*)d_in[0];
    const float* Wqkv = (const float*)d_in[1];
    const float* bqkv = (const float*)d_in[2];
    const float* Wout = (const float*)d_in[3];
    const float* bout = (const float*)d_in[4];
    float* out = (float*)d_out;

    // Idempotent; first (uncaptured) correctness call sets it, so a no-op
    // during capture is harmless.
    cudaFuncSetAttribute(flash_attn, cudaFuncAttributeMaxDynamicSharedMemorySize,
                         FLASH_SMEM_BYTES);

    qkv_gemm<<<dim3(SEQ / 128, MQKV / 128, BATCH), 256>>>(Wqkv, x, bqkv);
    flash_attn<<<dim3(SEQ / 128, BATCH * NH), 256, FLASH_SMEM_BYTES>>>();
    out_gemm<<<dim3(SEQ / 128, CDIM / 128, BATCH), 256>>>(Wout, bout, out);
}

// round 5
// speedup vs baseline: 2.6462x; 2.6462x over previous
#include <cuda_runtime.h>
#include <math.h>

// ---------------------------------------------------------------------------
// MultiHeadSelfAttention via tf32 tensor-core mma.sync (m16n8k8), fp32 accum.
//   1) qkv_gemm : W[1536,512] @ x[b,512,2304] + bias -> Q/K/V scratch [bh,d,s]
//                 (Q pre-scaled by HD^-0.5)
//   2) flash_attn: 128q x 128t tiles, softmax in registers on mma C-frags,
//                 P routed through smem (aliasing the K tile buffer)
//   3) out_gemm : Wout[512,512] @ O + bias -> d_out
// ---------------------------------------------------------------------------

#define BATCH 4
#define CDIM  512
#define SEQ   2304
#define NH    8
#define HD    64
#define MQKV  1536

#define SCRATCH_ELEMS (BATCH * CDIM * SEQ)
__device__ float g_Q[SCRATCH_ELEMS];
__device__ float g_K[SCRATCH_ELEMS];
__device__ float g_V[SCRATCH_ELEMS];
__device__ float g_O[SCRATCH_ELEMS];

// fp32 -> tf32 (round-to-nearest) as raw b32 bits
__device__ __forceinline__ unsigned f2tf(float x) {
    unsigned r;
    asm("cvt.rna.tf32.f32 %0, %1;" : "=r"(r) : "f"(x));
    return r;
}

// D += A*B, m16n8k8 tf32. c: 4 fp32, a: 4 b32, b: 2 b32.
__device__ __forceinline__ void mma_tf32(float* c, const unsigned* a,
                                         unsigned b0, unsigned b1) {
    asm volatile(
        "mma.sync.aligned.m16n8k8.row.col.f32.tf32.tf32.f32 "
        "{%0,%1,%2,%3}, {%4,%5,%6,%7}, {%8,%9}, {%0,%1,%2,%3};"
        : "+f"(c[0]), "+f"(c[1]), "+f"(c[2]), "+f"(c[3])
        : "r"(a[0]), "r"(a[1]), "r"(a[2]), "r"(a[3]), "r"(b0), "r"(b1));
}

// ---------------------------------------------------------------------------
// Projection GEMM core: 128x128 block tile, BK=16, 8 warps (2x4), each warp
// 64m x 32n = 4x4 m16n8k8 tiles. A=W [M,K] row-major, B=X [K,N].
// Ws[m][k] stride 20 (bank-bijective a-frag loads); Xs[k][n] stride 136.
// ---------------------------------------------------------------------------
#define WLD 20
#define XLD 136

#define PROJ_MAINLOOP(W_, XB_)                                                 \
    float acc[4][4][4];                                                        \
    _Pragma("unroll") for (int i = 0; i < 4; i++)                              \
    _Pragma("unroll") for (int j = 0; j < 4; j++)                              \
    _Pragma("unroll") for (int k = 0; k < 4; k++) acc[i][j][k] = 0.0f;         \
    const int lr = tid >> 1, lh = (tid & 1) * 8;                               \
    const int xr = tid >> 4, xc = (tid & 15) * 8;                              \
    for (int k0 = 0; k0 < CDIM; k0 += 16) {                                    \
        float4 w0 = *(const float4*)(W_ + (size_t)(m0 + lr) * CDIM + k0 + lh); \
        float4 w1 = *(const float4*)(W_ + (size_t)(m0 + lr) * CDIM + k0 + lh + 4);\
        float4 x0 = *(const float4*)(XB_ + (size_t)(k0 + xr) * SEQ + n0 + xc); \
        float4 x1 = *(const float4*)(XB_ + (size_t)(k0 + xr) * SEQ + n0 + xc + 4);\
        __syncthreads();                                                       \
        unsigned* wp = &Ws[lr * WLD + lh];                                     \
        wp[0] = f2tf(w0.x); wp[1] = f2tf(w0.y); wp[2] = f2tf(w0.z); wp[3] = f2tf(w0.w);\
        wp[4] = f2tf(w1.x); wp[5] = f2tf(w1.y); wp[6] = f2tf(w1.z); wp[7] = f2tf(w1.w);\
        unsigned* xp = &Xs[xr * XLD + xc];                                     \
        xp[0] = f2tf(x0.x); xp[1] = f2tf(x0.y); xp[2] = f2tf(x0.z); xp[3] = f2tf(x0.w);\
        xp[4] = f2tf(x1.x); xp[5] = f2tf(x1.y); xp[6] = f2tf(x1.z); xp[7] = f2tf(x1.w);\
        __syncthreads();                                                       \
        _Pragma("unroll")                                                      \
        for (int kk = 0; kk < 16; kk += 8) {                                   \
            unsigned afr[4][4];                                                \
            _Pragma("unroll") for (int tm = 0; tm < 4; tm++) {                 \
                const int row = wm + tm * 16;                                  \
                afr[tm][0] = Ws[(row + r) * WLD + kk + q];                     \
                afr[tm][1] = Ws[(row + r + 8) * WLD + kk + q];                 \
                afr[tm][2] = Ws[(row + r) * WLD + kk + q + 4];                 \
                afr[tm][3] = Ws[(row + r + 8) * WLD + kk + q + 4];             \
            }                                                                  \
            unsigned bfr[4][2];                                                \
            _Pragma("unroll") for (int tn = 0; tn < 4; tn++) {                 \
                const int col = wn + tn * 8 + r;                               \
                bfr[tn][0] = Xs[(kk + q) * XLD + col];                         \
                bfr[tn][1] = Xs[(kk + q + 4) * XLD + col];                     \
            }                                                                  \
            _Pragma("unroll") for (int tm = 0; tm < 4; tm++)                   \
            _Pragma("unroll") for (int tn = 0; tn < 4; tn++)                   \
                mma_tf32(acc[tm][tn], afr[tm], bfr[tn][0], bfr[tn][1]);        \
        }                                                                      \
    }

__global__ __launch_bounds__(256, 2) void qkv_gemm(
    const float* __restrict__ W, const float* __restrict__ X,
    const float* __restrict__ bias)
{
    __shared__ unsigned Ws[128 * WLD];
    __shared__ unsigned Xs[16 * XLD];

    const int tid = threadIdx.x;
    const int b = blockIdx.z, m0 = blockIdx.y * 128, n0 = blockIdx.x * 128;
    const int lane = tid & 31, warp = tid >> 5;
    const int q = lane & 3, r = lane >> 2;
    const int wm = (warp >> 2) * 64, wn = (warp & 3) * 32;
    const float* Xb = X + (size_t)b * CDIM * SEQ;

    PROJ_MAINLOOP(W, Xb)

    // route o -> (which,h,d); whole 128-row tile shares one 'which'
    const int which = m0 >> 9;
    float* dst = (which == 0) ? g_Q : (which == 1) ? g_K : g_V;
    const float qs = (which == 0) ? 0.125f : 1.0f;

#pragma unroll
    for (int tm = 0; tm < 4; tm++) {
        const int mA = m0 + wm + tm * 16 + r;
        const int mB = mA + 8;
        const float bvA = bias[mA], bvB = bias[mB];
        float* rowA = dst + ((size_t)b * CDIM + (mA & 511)) * SEQ;
        float* rowB = dst + ((size_t)b * CDIM + (mB & 511)) * SEQ;
#pragma unroll
        for (int tn = 0; tn < 4; tn++) {
            const int n = n0 + wn + tn * 8 + 2 * q;
            float2 vA = make_float2((acc[tm][tn][0] + bvA) * qs,
                                    (acc[tm][tn][1] + bvA) * qs);
            float2 vB = make_float2((acc[tm][tn][2] + bvB) * qs,
                                    (acc[tm][tn][3] + bvB) * qs);
            *(float2*)(rowA + n) = vA;
            *(float2*)(rowB + n) = vB;
        }
    }
}

__global__ __launch_bounds__(256, 2) void out_gemm(
    const float* __restrict__ W, const float* __restrict__ bias,
    float* __restrict__ Y)
{
    __shared__ unsigned Ws[128 * WLD];
    __shared__ unsigned Xs[16 * XLD];

    const int tid = threadIdx.x;
    const int b = blockIdx.z, m0 = blockIdx.y * 128, n0 = blockIdx.x * 128;
    const int lane = tid & 31, warp = tid >> 5;
    const int q = lane & 3, r = lane >> 2;
    const int wm = (warp >> 2) * 64, wn = (warp & 3) * 32;
    const float* Xb = g_O + (size_t)b * CDIM * SEQ;

    PROJ_MAINLOOP(W, Xb)

#pragma unroll
    for (int tm = 0; tm < 4; tm++) {
        const int mA = m0 + wm + tm * 16 + r;
        const int mB = mA + 8;
        const float bvA = bias[mA], bvB = bias[mB];
        float* rowA = Y + ((size_t)b * CDIM + mA) * SEQ;
        float* rowB = Y + ((size_t)b * CDIM + mB) * SEQ;
#pragma unroll
        for (int tn = 0; tn < 4; tn++) {
            const int n = n0 + wn + tn * 8 + 2 * q;
            *(float2*)(rowA + n) = make_float2(acc[tm][tn][0] + bvA,
                                               acc[tm][tn][1] + bvA);
            *(float2*)(rowB + n) = make_float2(acc[tm][tn][2] + bvB,
                                               acc[tm][tn][3] + bvB);
        }
    }
}

// ---------------------------------------------------------------------------
// Flash attention, tf32 mma. grid=(18, 32), 256 thr (8 warps).
// Warp w owns score/O rows 16w..16w+15 -> softmax fully in registers.
// Smem (words): Qs[64][136] | KP union(Ks[64][136], Ps[128][132]) | Vs[64][132]
// All fragment LDS patterns are 32-bank bijections.
// ---------------------------------------------------------------------------
#define QLD 136
#define KLD 136
#define VLD 132
#define PST 132
#define OFF_KP (64 * QLD)                 // 8704
#define OFF_V  (OFF_KP + 128 * PST)       // 25600
#define FLASH_WORDS (OFF_V + 64 * VLD)    // 34048
#define FLASH_BYTES (FLASH_WORDS * 4)     // 136192

__global__ __launch_bounds__(256, 1) void flash_attn()
{
    extern __shared__ unsigned smw[];
    unsigned* Qs  = smw;
    unsigned* KPs = smw + OFF_KP;
    unsigned* Vs  = smw + OFF_V;

    const int tid  = threadIdx.x;
    const int warp = tid >> 5, lane = tid & 31;
    const int q = lane & 3, r = lane >> 2;
    const int rw = warp * 16;
    const int bh = blockIdx.y;
    const int s0 = blockIdx.x * 128;

    const float* Qg = g_Q + (size_t)bh * HD * SEQ;
    const float* Kg = g_K + (size_t)bh * HD * SEQ;
    const float* Vg = g_V + (size_t)bh * HD * SEQ;
    float*       Og = g_O + (size_t)bh * HD * SEQ;

    const int ld_d = tid >> 2;            // 0..63
    const int ld_c = (tid & 3) * 32;      // 0,32,64,96

    // Q tile once: [d][s] -> Qs[d*136 + s]
#pragma unroll
    for (int f = 0; f < 8; f++) {
        float4 v = *(const float4*)(Qg + (size_t)ld_d * SEQ + s0 + ld_c + f * 4);
        unsigned* p = &Qs[ld_d * QLD + ld_c + f * 4];
        p[0] = f2tf(v.x); p[1] = f2tf(v.y); p[2] = f2tf(v.z); p[3] = f2tf(v.w);
    }

    float O[8][4];
#pragma unroll
    for (int i = 0; i < 8; i++)
#pragma unroll
        for (int j = 0; j < 4; j++) O[i][j] = 0.0f;

    float mA = -1e30f, mB = -1e30f, lA = 0.0f, lB = 0.0f;

    for (int t0 = 0; t0 < SEQ; t0 += 128) {
        // prefetch K,V tile into regs (before the sync that frees smem)
        float4 kreg[8], vreg[8];
#pragma unroll
        for (int f = 0; f < 8; f++) {
            kreg[f] = *(const float4*)(Kg + (size_t)ld_d * SEQ + t0 + ld_c + f * 4);
            vreg[f] = *(const float4*)(Vg + (size_t)ld_d * SEQ + t0 + ld_c + f * 4);
        }
        __syncthreads();   // prior PV done reading Ps/Vs (and Q ready on iter 0)
#pragma unroll
        for (int f = 0; f < 8; f++) {
            unsigned* pk = &KPs[ld_d * KLD + ld_c + f * 4];
            pk[0] = f2tf(kreg[f].x); pk[1] = f2tf(kreg[f].y);
            pk[2] = f2tf(kreg[f].z); pk[3] = f2tf(kreg[f].w);
            unsigned* pv = &Vs[ld_d * VLD + ld_c + f * 4];
            pv[0] = f2tf(vreg[f].x); pv[1] = f2tf(vreg[f].y);
            pv[2] = f2tf(vreg[f].z); pv[3] = f2tf(vreg[f].w);
        }
        __syncthreads();

        // score: S[16 rows owned by warp][128 t] = Q . K
        float S[16][4];
#pragma unroll
        for (int tn = 0; tn < 16; tn++)
#pragma unroll
            for (int j = 0; j < 4; j++) S[tn][j] = 0.0f;

#pragma unroll
        for (int ks = 0; ks < 8; ks++) {
            const int k0 = ks * 8;
            unsigned a[4];
            a[0] = Qs[(k0 + q) * QLD + rw + r];
            a[1] = Qs[(k0 + q) * QLD + rw + r + 8];
            a[2] = Qs[(k0 + q + 4) * QLD + rw + r];
            a[3] = Qs[(k0 + q + 4) * QLD + rw + r + 8];
#pragma unroll
            for (int tn = 0; tn < 16; tn++) {
                unsigned b0 = KPs[(k0 + q) * KLD + tn * 8 + r];
                unsigned b1 = KPs[(k0 + q + 4) * KLD + tn * 8 + r];
                mma_tf32(S[tn], a, b0, b1);
            }
        }

        // online softmax in registers (rows rw+r and rw+r+8)
        float mxA = -1e30f, mxB = -1e30f;
#pragma unroll
        for (int tn = 0; tn < 16; tn++) {
            mxA = fmaxf(mxA, fmaxf(S[tn][0], S[tn][1]));
            mxB = fmaxf(mxB, fmaxf(S[tn][2], S[tn][3]));
        }
        mxA = fmaxf(mxA, __shfl_xor_sync(0xffffffffu, mxA, 1));
        mxA = fmaxf(mxA, __shfl_xor_sync(0xffffffffu, mxA, 2));
        mxB = fmaxf(mxB, __shfl_xor_sync(0xffffffffu, mxB, 1));
        mxB = fmaxf(mxB, __shfl_xor_sync(0xffffffffu, mxB, 2));

        const float mnA = fmaxf(mA, mxA), mnB = fmaxf(mB, mxB);
        const float cA = __expf(mA - mnA), cB = __expf(mB - mnB);
        float sA = 0.0f, sB = 0.0f;
#pragma unroll
        for (int tn = 0; tn < 16; tn++) {
            S[tn][0] = __expf(S[tn][0] - mnA); sA += S[tn][0];
            S[tn][1] = __expf(S[tn][1] - mnA); sA += S[tn][1];
            S[tn][2] = __expf(S[tn][2] - mnB); sB += S[tn][2];
            S[tn][3] = __expf(S[tn][3] - mnB); sB += S[tn][3];
        }
        sA += __shfl_xor_sync(0xffffffffu, sA, 1);
        sA += __shfl_xor_sync(0xffffffffu, sA, 2);
        sB += __shfl_xor_sync(0xffffffffu, sB, 1);
        sB += __shfl_xor_sync(0xffffffffu, sB, 2);

        lA = lA * cA + sA;  lB = lB * cB + sB;
        mA = mnA;           mB = mnB;
#pragma unroll
        for (int to = 0; to < 8; to++) {
            O[to][0] *= cA; O[to][1] *= cA;
            O[to][2] *= cB; O[to][3] *= cB;
        }

        __syncthreads();   // all warps finished reading the K tile

        // P (tf32) into the K buffer: Ps[sq][t] stride 132
#pragma unroll
        for (int tn = 0; tn < 16; tn++) {
            const int t = tn * 8 + 2 * q;
            uint2 pa = make_uint2(f2tf(S[tn][0]), f2tf(S[tn][1]));
            uint2 pb = make_uint2(f2tf(S[tn][2]), f2tf(S[tn][3]));
            *(uint2*)&KPs[(rw + r) * PST + t]     = pa;
            *(uint2*)&KPs[(rw + r + 8) * PST + t] = pb;
        }
        __syncthreads();

        // O[sq][d] += P . V
#pragma unroll
        for (int ks = 0; ks < 16; ks++) {
            const int k0 = ks * 8;
            unsigned a[4];
            a[0] = KPs[(rw + r) * PST + k0 + q];
            a[1] = KPs[(rw + r + 8) * PST + k0 + q];
            a[2] = KPs[(rw + r) * PST + k0 + q + 4];
            a[3] = KPs[(rw + r + 8) * PST + k0 + q + 4];
#pragma unroll
            for (int to = 0; to < 8; to++) {
                unsigned b0 = Vs[(to * 8 + r) * VLD + k0 + q];
                unsigned b1 = Vs[(to * 8 + r) * VLD + k0 + q + 4];
                mma_tf32(O[to], a, b0, b1);
            }
        }
    }

    // normalize + store O[b,h,d,s]
    const float iA = 1.0f / lA, iB = 1.0f / lB;
    const int sA0 = s0 + rw + r, sB0 = sA0 + 8;
#pragma unroll
    for (int to = 0; to < 8; to++) {
        const int d0 = to * 8 + 2 * q;
        Og[(size_t)d0 * SEQ + sA0]       = O[to][0] * iA;
        Og[(size_t)(d0 + 1) * SEQ + sA0] = O[to][1] * iA;
        Og[(size_t)d0 * SEQ + sB0]       = O[to][2] * iB;
        Og[(size_t)(d0 + 1) * SEQ + sB0] = O[to][3] * iB;
    }
}

// ---------------------------------------------------------------------------
extern "C" void kernel_launch(void* const* d_in, const int* in_sizes, int n_in,
                              void* d_out, int out_size)
{
    const float* x    = (const float*)d_in[0];
    const float* Wqkv = (const float*)d_in[1];
    const float* bqkv = (const float*)d_in[2];
    const float* Wout = (const float*)d_in[3];
    const float* bout = (const float*)d_in[4];
    float* out = (float*)d_out;

    cudaFuncSetAttribute(flash_attn, cudaFuncAttributeMaxDynamicSharedMemorySize,
                         FLASH_BYTES);

    qkv_gemm<<<dim3(SEQ / 128, MQKV / 128, BATCH), 256>>>(Wqkv, x, bqkv);
    flash_attn<<<dim3(SEQ / 128, BATCH * NH), 256, FLASH_BYTES>>>();
    out_gemm<<<dim3(SEQ / 128, CDIM / 128, BATCH), 256>>>(Wout, bout, out);
}

// round 6
// speedup vs baseline: 2.9724x; 1.1233x over previous
#include <cuda_runtime.h>
#include <math.h>

// ---------------------------------------------------------------------------
// MultiHeadSelfAttention via tf32 mma.sync (m16n8k8), fp32 accumulate.
//   qkv_gemm  : W[1536,512] @ x[b,512,2304] + bias -> Q/K/V [bh,d,s], Q*0.125
//   flash_attn: 128q x 64t tiles, Q-frags in registers, P aliases Q staging,
//               K/V gmem prefetch one tile ahead, 2 CTAs/SM.
//   out_gemm  : Wout[512,512] @ O + bias -> d_out
// ---------------------------------------------------------------------------

#define BATCH 4
#define CDIM  512
#define SEQ   2304
#define NH    8
#define HD    64
#define MQKV  1536

#define SCRATCH_ELEMS (BATCH * CDIM * SEQ)
__device__ float g_Q[SCRATCH_ELEMS];
__device__ float g_K[SCRATCH_ELEMS];
__device__ float g_V[SCRATCH_ELEMS];
__device__ float g_O[SCRATCH_ELEMS];

__device__ __forceinline__ unsigned f2tf(float x) {
    unsigned r;
    asm("cvt.rna.tf32.f32 %0, %1;" : "=r"(r) : "f"(x));
    return r;
}

__device__ __forceinline__ void mma_tf32(float* c, const unsigned* a,
                                         unsigned b0, unsigned b1) {
    asm volatile(
        "mma.sync.aligned.m16n8k8.row.col.f32.tf32.tf32.f32 "
        "{%0,%1,%2,%3}, {%4,%5,%6,%7}, {%8,%9}, {%0,%1,%2,%3};"
        : "+f"(c[0]), "+f"(c[1]), "+f"(c[2]), "+f"(c[3])
        : "r"(a[0]), "r"(a[1]), "r"(a[2]), "r"(a[3]), "r"(b0), "r"(b1));
}

// ---------------------------------------------------------------------------
// Projection GEMM core: 128x128 tile, BK=16, 8 warps (2x4), warp = 64m x 32n.
// Register prefetch of the next BK slab overlaps gmem latency with mma.
// ---------------------------------------------------------------------------
#define WLD 20
#define XLD 136

#define PROJ_MAINLOOP(W_, XB_)                                                 \
    float acc[4][4][4];                                                        \
    _Pragma("unroll") for (int i = 0; i < 4; i++)                              \
    _Pragma("unroll") for (int j = 0; j < 4; j++)                              \
    _Pragma("unroll") for (int k = 0; k < 4; k++) acc[i][j][k] = 0.0f;         \
    const int lr = tid >> 1, lh = (tid & 1) * 8;                               \
    const int xr = tid >> 4, xc = (tid & 15) * 8;                              \
    float4 w0 = *(const float4*)(W_ + (size_t)(m0 + lr) * CDIM + lh);          \
    float4 w1 = *(const float4*)(W_ + (size_t)(m0 + lr) * CDIM + lh + 4);      \
    float4 x0 = *(const float4*)(XB_ + (size_t)xr * SEQ + n0 + xc);            \
    float4 x1 = *(const float4*)(XB_ + (size_t)xr * SEQ + n0 + xc + 4);        \
    for (int k0 = 0; k0 < CDIM; k0 += 16) {                                    \
        __syncthreads();                                                       \
        unsigned* wp = &Ws[lr * WLD + lh];                                     \
        wp[0] = f2tf(w0.x); wp[1] = f2tf(w0.y); wp[2] = f2tf(w0.z); wp[3] = f2tf(w0.w);\
        wp[4] = f2tf(w1.x); wp[5] = f2tf(w1.y); wp[6] = f2tf(w1.z); wp[7] = f2tf(w1.w);\
        unsigned* xp = &Xs[xr * XLD + xc];                                     \
        xp[0] = f2tf(x0.x); xp[1] = f2tf(x0.y); xp[2] = f2tf(x0.z); xp[3] = f2tf(x0.w);\
        xp[4] = f2tf(x1.x); xp[5] = f2tf(x1.y); xp[6] = f2tf(x1.z); xp[7] = f2tf(x1.w);\
        __syncthreads();                                                       \
        if (k0 + 16 < CDIM) {                                                  \
            w0 = *(const float4*)(W_ + (size_t)(m0 + lr) * CDIM + k0 + 16 + lh);      \
            w1 = *(const float4*)(W_ + (size_t)(m0 + lr) * CDIM + k0 + 16 + lh + 4);  \
            x0 = *(const float4*)(XB_ + (size_t)(k0 + 16 + xr) * SEQ + n0 + xc);      \
            x1 = *(const float4*)(XB_ + (size_t)(k0 + 16 + xr) * SEQ + n0 + xc + 4);  \
        }                                                                      \
        _Pragma("unroll")                                                      \
        for (int kk = 0; kk < 16; kk += 8) {                                   \
            unsigned afr[4][4];                                                \
            _Pragma("unroll") for (int tm = 0; tm < 4; tm++) {                 \
                const int row = wm + tm * 16;                                  \
                afr[tm][0] = Ws[(row + r) * WLD + kk + q];                     \
                afr[tm][1] = Ws[(row + r + 8) * WLD + kk + q];                 \
                afr[tm][2] = Ws[(row + r) * WLD + kk + q + 4];                 \
                afr[tm][3] = Ws[(row + r + 8) * WLD + kk + q + 4];             \
            }                                                                  \
            unsigned bfr[4][2];                                                \
            _Pragma("unroll") for (int tn = 0; tn < 4; tn++) {                 \
                const int col = wn + tn * 8 + r;                               \
                bfr[tn][0] = Xs[(kk + q) * XLD + col];                         \
                bfr[tn][1] = Xs[(kk + q + 4) * XLD + col];                     \
            }                                                                  \
            _Pragma("unroll") for (int tm = 0; tm < 4; tm++)                   \
            _Pragma("unroll") for (int tn = 0; tn < 4; tn++)                   \
                mma_tf32(acc[tm][tn], afr[tm], bfr[tn][0], bfr[tn][1]);        \
        }                                                                      \
    }

__global__ __launch_bounds__(256, 2) void qkv_gemm(
    const float* __restrict__ W, const float* __restrict__ X,
    const float* __restrict__ bias)
{
    __shared__ unsigned Ws[128 * WLD];
    __shared__ unsigned Xs[16 * XLD];

    const int tid = threadIdx.x;
    const int b = blockIdx.z, m0 = blockIdx.y * 128, n0 = blockIdx.x * 128;
    const int lane = tid & 31, warp = tid >> 5;
    const int q = lane & 3, r = lane >> 2;
    const int wm = (warp >> 2) * 64, wn = (warp & 3) * 32;
    const float* Xb = X + (size_t)b * CDIM * SEQ;

    PROJ_MAINLOOP(W, Xb)

    const int which = m0 >> 9;
    float* dst = (which == 0) ? g_Q : (which == 1) ? g_K : g_V;
    const float qs = (which == 0) ? 0.125f : 1.0f;

#pragma unroll
    for (int tm = 0; tm < 4; tm++) {
        const int mA = m0 + wm + tm * 16 + r;
        const int mB = mA + 8;
        const float bvA = bias[mA], bvB = bias[mB];
        float* rowA = dst + ((size_t)b * CDIM + (mA & 511)) * SEQ;
        float* rowB = dst + ((size_t)b * CDIM + (mB & 511)) * SEQ;
#pragma unroll
        for (int tn = 0; tn < 4; tn++) {
            const int n = n0 + wn + tn * 8 + 2 * q;
            *(float2*)(rowA + n) = make_float2((acc[tm][tn][0] + bvA) * qs,
                                               (acc[tm][tn][1] + bvA) * qs);
            *(float2*)(rowB + n) = make_float2((acc[tm][tn][2] + bvB) * qs,
                                               (acc[tm][tn][3] + bvB) * qs);
        }
    }
}

__global__ __launch_bounds__(256, 2) void out_gemm(
    const float* __restrict__ W, const float* __restrict__ bias,
    float* __restrict__ Y)
{
    __shared__ unsigned Ws[128 * WLD];
    __shared__ unsigned Xs[16 * XLD];

    const int tid = threadIdx.x;
    const int b = blockIdx.z, m0 = blockIdx.y * 128, n0 = blockIdx.x * 128;
    const int lane = tid & 31, warp = tid >> 5;
    const int q = lane & 3, r = lane >> 2;
    const int wm = (warp >> 2) * 64, wn = (warp & 3) * 32;
    const float* Xb = g_O + (size_t)b * CDIM * SEQ;

    PROJ_MAINLOOP(W, Xb)

#pragma unroll
    for (int tm = 0; tm < 4; tm++) {
        const int mA = m0 + wm + tm * 16 + r;
        const int mB = mA + 8;
        const float bvA = bias[mA], bvB = bias[mB];
        float* rowA = Y + ((size_t)b * CDIM + mA) * SEQ;
        float* rowB = Y + ((size_t)b * CDIM + mB) * SEQ;
#pragma unroll
        for (int tn = 0; tn < 4; tn++) {
            const int n = n0 + wn + tn * 8 + 2 * q;
            *(float2*)(rowA + n) = make_float2(acc[tm][tn][0] + bvA,
                                               acc[tm][tn][1] + bvA);
            *(float2*)(rowB + n) = make_float2(acc[tm][tn][2] + bvB,
                                               acc[tm][tn][3] + bvB);
        }
    }
}

// ---------------------------------------------------------------------------
// Flash attention, tf32 mma. grid=(18, 32), 256 thr (8 warps), 2 CTAs/SM.
// 128 q-rows per block (warp w owns rows 16w..16w+15), 64-key tiles.
// Smem (words): QP union( Qstage[64][136], P[128][68] ) = 8704
//             | Ks[64][72] = 4608 | Vs[64][68] = 4352   -> 69 KB
// Fragment bank maps: K b-frag 8q+r, P a-frag 4r+q, V b-frag 4r+q (bijective).
// 2 block syncs per tile; P-store -> PV needs only __syncwarp (own rows).
// ---------------------------------------------------------------------------
#define QLD 136
#define KLD 72
#define VLD 68
#define PST 68
#define OFF_K 8704
#define OFF_V (OFF_K + 64 * KLD)            // 13312
#define FLASH_WORDS (OFF_V + 64 * VLD)      // 17664
#define FLASH_BYTES (FLASH_WORDS * 4)       // 70656

__global__ __launch_bounds__(256, 2) void flash_attn()
{
    extern __shared__ unsigned smw[];
    unsigned* QP = smw;           // Q staging, later P
    unsigned* Ks = smw + OFF_K;
    unsigned* Vs = smw + OFF_V;

    const int tid  = threadIdx.x;
    const int warp = tid >> 5, lane = tid & 31;
    const int q = lane & 3, r = lane >> 2;
    const int rw = warp * 16;
    const int bh = blockIdx.y;
    const int s0 = blockIdx.x * 128;

    const float* Qg = g_Q + (size_t)bh * HD * SEQ;
    const float* Kg = g_K + (size_t)bh * HD * SEQ;
    const float* Vg = g_V + (size_t)bh * HD * SEQ;
    float*       Og = g_O + (size_t)bh * HD * SEQ;

    const int d   = tid >> 2;           // 0..63
    const int cq  = (tid & 3) * 16;     // 64-col loader lane offset
    const int cq2 = (tid & 3) * 32;     // 128-col (Q) loader lane offset

    // ---- Q: stage once, pick up fragments into registers, free the buffer.
#pragma unroll
    for (int f = 0; f < 8; f++) {
        float4 v = *(const float4*)(Qg + (size_t)d * SEQ + s0 + cq2 + f * 4);
        unsigned* p = &QP[d * QLD + cq2 + f * 4];
        p[0] = f2tf(v.x); p[1] = f2tf(v.y); p[2] = f2tf(v.z); p[3] = f2tf(v.w);
    }
    __syncthreads();
    unsigned qa[8][4];
#pragma unroll
    for (int ks = 0; ks < 8; ks++) {
        qa[ks][0] = QP[(ks * 8 + q) * QLD + rw + r];
        qa[ks][1] = QP[(ks * 8 + q) * QLD + rw + r + 8];
        qa[ks][2] = QP[(ks * 8 + q + 4) * QLD + rw + r];
        qa[ks][3] = QP[(ks * 8 + q + 4) * QLD + rw + r + 8];
    }

    float O[8][4];
#pragma unroll
    for (int i = 0; i < 8; i++)
#pragma unroll
        for (int j = 0; j < 4; j++) O[i][j] = 0.0f;

    float mA = -1e30f, mB = -1e30f, lA = 0.0f, lB = 0.0f;

    // prefetch first K/V tile
    float4 kreg[4], vreg[4];
#pragma unroll
    for (int f = 0; f < 4; f++) {
        kreg[f] = *(const float4*)(Kg + (size_t)d * SEQ + cq + f * 4);
        vreg[f] = *(const float4*)(Vg + (size_t)d * SEQ + cq + f * 4);
    }

    for (int t0 = 0; t0 < SEQ; t0 += 64) {
        __syncthreads();   // A: K/V/P buffers free (prev tile fully consumed)
#pragma unroll
        for (int f = 0; f < 4; f++) {
            unsigned* pk = &Ks[d * KLD + cq + f * 4];
            pk[0] = f2tf(kreg[f].x); pk[1] = f2tf(kreg[f].y);
            pk[2] = f2tf(kreg[f].z); pk[3] = f2tf(kreg[f].w);
            unsigned* pv = &Vs[d * VLD + cq + f * 4];
            pv[0] = f2tf(vreg[f].x); pv[1] = f2tf(vreg[f].y);
            pv[2] = f2tf(vreg[f].z); pv[3] = f2tf(vreg[f].w);
        }
        __syncthreads();   // B: K/V visible

        // S[16 warp rows][64 t] = Q . K
        float S[8][4];
#pragma unroll
        for (int tn = 0; tn < 8; tn++)
#pragma unroll
            for (int j = 0; j < 4; j++) S[tn][j] = 0.0f;

#pragma unroll
        for (int ks = 0; ks < 8; ks++) {
            const int k0 = ks * 8;
#pragma unroll
            for (int tn = 0; tn < 8; tn++) {
                unsigned b0 = Ks[(k0 + q) * KLD + tn * 8 + r];
                unsigned b1 = Ks[(k0 + q + 4) * KLD + tn * 8 + r];
                mma_tf32(S[tn], qa[ks], b0, b1);
            }
        }

        // online softmax in registers (rows rw+r and rw+r+8)
        float mxA = -1e30f, mxB = -1e30f;
#pragma unroll
        for (int tn = 0; tn < 8; tn++) {
            mxA = fmaxf(mxA, fmaxf(S[tn][0], S[tn][1]));
            mxB = fmaxf(mxB, fmaxf(S[tn][2], S[tn][3]));
        }
        mxA = fmaxf(mxA, __shfl_xor_sync(0xffffffffu, mxA, 1));
        mxA = fmaxf(mxA, __shfl_xor_sync(0xffffffffu, mxA, 2));
        mxB = fmaxf(mxB, __shfl_xor_sync(0xffffffffu, mxB, 1));
        mxB = fmaxf(mxB, __shfl_xor_sync(0xffffffffu, mxB, 2));

        const float mnA = fmaxf(mA, mxA), mnB = fmaxf(mB, mxB);
        const float cA = __expf(mA - mnA), cB = __expf(mB - mnB);
        float sA = 0.0f, sB = 0.0f;
#pragma unroll
        for (int tn = 0; tn < 8; tn++) {
            S[tn][0] = __expf(S[tn][0] - mnA); sA += S[tn][0];
            S[tn][1] = __expf(S[tn][1] - mnA); sA += S[tn][1];
            S[tn][2] = __expf(S[tn][2] - mnB); sB += S[tn][2];
            S[tn][3] = __expf(S[tn][3] - mnB); sB += S[tn][3];
        }
        sA += __shfl_xor_sync(0xffffffffu, sA, 1);
        sA += __shfl_xor_sync(0xffffffffu, sA, 2);
        sB += __shfl_xor_sync(0xffffffffu, sB, 1);
        sB += __shfl_xor_sync(0xffffffffu, sB, 2);

        lA = lA * cA + sA;  lB = lB * cB + sB;
        mA = mnA;           mB = mnB;
#pragma unroll
        for (int to = 0; to < 8; to++) {
            O[to][0] *= cA; O[to][1] *= cA;
            O[to][2] *= cB; O[to][3] *= cB;
        }

        // P into the freed Q-staging buffer (own warp rows only)
#pragma unroll
        for (int tn = 0; tn < 8; tn++) {
            const int t = tn * 8 + 2 * q;
            *(uint2*)&QP[(rw + r) * PST + t] =
                make_uint2(f2tf(S[tn][0]), f2tf(S[tn][1]));
            *(uint2*)&QP[(rw + r + 8) * PST + t] =
                make_uint2(f2tf(S[tn][2]), f2tf(S[tn][3]));
        }

        // prefetch next K/V tile (S registers are dead now)
        if (t0 + 64 < SEQ) {
#pragma unroll
            for (int f = 0; f < 4; f++) {
                kreg[f] = *(const float4*)(Kg + (size_t)d * SEQ + t0 + 64 + cq + f * 4);
                vreg[f] = *(const float4*)(Vg + (size_t)d * SEQ + t0 + 64 + cq + f * 4);
            }
        }
        __syncwarp();   // P visible within the warp (PV reads own rows only)

        // O[16 warp rows][64 d] += P . V
#pragma unroll
        for (int ks = 0; ks < 8; ks++) {
            const int k0 = ks * 8;
            unsigned a[4];
            a[0] = QP[(rw + r) * PST + k0 + q];
            a[1] = QP[(rw + r + 8) * PST + k0 + q];
            a[2] = QP[(rw + r) * PST + k0 + q + 4];
            a[3] = QP[(rw + r + 8) * PST + k0 + q + 4];
#pragma unroll
            for (int to = 0; to < 8; to++) {
                unsigned b0 = Vs[(to * 8 + r) * VLD + k0 + q];
                unsigned b1 = Vs[(to * 8 + r) * VLD + k0 + q + 4];
                mma_tf32(O[to], a, b0, b1);
            }
        }
    }

    // normalize + store O[b,h,d,s]
    const float iA = 1.0f / lA, iB = 1.0f / lB;
    const int sA0 = s0 + rw + r, sB0 = sA0 + 8;
#pragma unroll
    for (int to = 0; to < 8; to++) {
        const int d0 = to * 8 + 2 * q;
        Og[(size_t)d0 * SEQ + sA0]       = O[to][0] * iA;
        Og[(size_t)(d0 + 1) * SEQ + sA0] = O[to][1] * iA;
        Og[(size_t)d0 * SEQ + sB0]       = O[to][2] * iB;
        Og[(size_t)(d0 + 1) * SEQ + sB0] = O[to][3] * iB;
    }
}

// ---------------------------------------------------------------------------
extern "C" void kernel_launch(void* const* d_in, const int* in_sizes, int n_in,
                              void* d_out, int out_size)
{
    const float* x    = (const float*)d_in[0];
    const float* Wqkv = (const float*)d_in[1];
    const float* bqkv = (const float*)d_in[2];
    const float* Wout = (const float*)d_in[3];
    const float* bout = (const float*)d_in[4];
    float* out = (float*)d_out;

    cudaFuncSetAttribute(flash_attn, cudaFuncAttributeMaxDynamicSharedMemorySize,
                         FLASH_BYTES);

    qkv_gemm<<<dim3(SEQ / 128, MQKV / 128, BATCH), 256>>>(Wqkv, x, bqkv);
    flash_attn<<<dim3(SEQ / 128, BATCH * NH), 256, FLASH_BYTES>>>();
    out_gemm<<<dim3(SEQ / 128, CDIM / 128, BATCH), 256>>>(Wout, bout, out);
}

// round 7
// speedup vs baseline: 3.4627x; 1.1649x over previous
#include <cuda_runtime.h>

// ---------------------------------------------------------------------------
// MultiHeadSelfAttention, tf32 mma.sync + cp.async everywhere.
//   prep      : pre-convert x, Wqkv, Wout to tf32 bits (one-time, ~8us)
//   qkv_gemm  : tf32 W @ tf32 X + bias -> Q/K/V scratch as tf32 bits, Q*0.125
//   flash_attn: 128q x 64t tiles, Q-frags in regs, double-buffered cp.async
//               K/V, P aliases Q staging, softmax in registers.
//   out_gemm  : tf32 Wout @ tf32 O + bias -> f32 d_out
// All conversions happen exactly once per value (same rounding points as R6).
// ---------------------------------------------------------------------------

#define BATCH 4
#define CDIM  512
#define SEQ   2304
#define NH    8
#define HD    64
#define MQKV  1536
#define SCR   (BATCH * CDIM * SEQ)

__device__ __align__(16) unsigned g_Q[SCR];
__device__ __align__(16) unsigned g_K[SCR];
__device__ __align__(16) unsigned g_V[SCR];
__device__ __align__(16) unsigned g_O[SCR];
__device__ __align__(16) unsigned g_Xt[SCR];
__device__ __align__(16) unsigned g_Wqt[MQKV * CDIM];
__device__ __align__(16) unsigned g_Wot[CDIM * CDIM];

__device__ __forceinline__ unsigned f2tf(float x) {
    unsigned r;
    asm("cvt.rna.tf32.f32 %0, %1;" : "=r"(r) : "f"(x));
    return r;
}

__device__ __forceinline__ void mma_tf32(float* c, const unsigned* a,
                                         unsigned b0, unsigned b1) {
    asm volatile(
        "mma.sync.aligned.m16n8k8.row.col.f32.tf32.tf32.f32 "
        "{%0,%1,%2,%3}, {%4,%5,%6,%7}, {%8,%9}, {%0,%1,%2,%3};"
        : "+f"(c[0]), "+f"(c[1]), "+f"(c[2]), "+f"(c[3])
        : "r"(a[0]), "r"(a[1]), "r"(a[2]), "r"(a[3]), "r"(b0), "r"(b1));
}

__device__ __forceinline__ void cp16(unsigned* dst, const unsigned* src) {
    unsigned da = (unsigned)__cvta_generic_to_shared(dst);
    asm volatile("cp.async.cg.shared.global [%0], [%1], 16;"
                 :: "r"(da), "l"(src));
}
__device__ __forceinline__ void cpcommit() {
    asm volatile("cp.async.commit_group;");
}
template <int N> __device__ __forceinline__ void cpwait() {
    asm volatile("cp.async.wait_group %0;" :: "n"(N));
}

// ---------------------------------------------------------------------------
// prep: fp32 -> tf32 bit conversion of x, Wqkv, Wout.
// ---------------------------------------------------------------------------
__global__ void prep(const float* __restrict__ x,
                     const float* __restrict__ Wqkv,
                     const float* __restrict__ Wout)
{
    const int stride = gridDim.x * blockDim.x;
    const int i0 = blockIdx.x * blockDim.x + threadIdx.x;
    for (int i = i0; i < SCR; i += stride)          g_Xt[i]  = f2tf(x[i]);
    for (int i = i0; i < MQKV * CDIM; i += stride)  g_Wqt[i] = f2tf(Wqkv[i]);
    for (int i = i0; i < CDIM * CDIM; i += stride)  g_Wot[i] = f2tf(Wout[i]);
}

// ---------------------------------------------------------------------------
// Projection GEMM: 128x128 tile, BK=16, double-buffered cp.async stages.
// 8 warps (2x4), warp = 64m x 32n. Stage = Ws[128][20] + Xs[16][136].
// ---------------------------------------------------------------------------
#define WLD 20
#define XLD 136
#define PSTG 4736   // 128*20 + 16*136 words per stage

#define PROJ_ISSUE(base_, k0_)                                                 \
    {                                                                          \
        unsigned* Wss = (base_);                                               \
        unsigned* Xss = (base_) + 128 * WLD;                                   \
        _Pragma("unroll") for (int j = 0; j < 2; j++) {                        \
            const int c = tid * 2 + j;                                         \
            const int m = c >> 2, kk = (c & 3) * 4;                            \
            cp16(Wss + m * WLD + kk, Wg + (size_t)m * CDIM + (k0_) + kk);      \
        }                                                                      \
        _Pragma("unroll") for (int j = 0; j < 2; j++) {                        \
            const int c = tid * 2 + j;                                         \
            const int kr = c >> 5, nc = (c & 31) * 4;                          \
            cp16(Xss + kr * XLD + nc, Xg + (size_t)((k0_) + kr) * SEQ + nc);   \
        }                                                                      \
        cpcommit();                                                            \
    }

#define PROJ_MAINLOOP()                                                        \
    float acc[4][4][4];                                                        \
    _Pragma("unroll") for (int i = 0; i < 4; i++)                              \
    _Pragma("unroll") for (int j = 0; j < 4; j++)                              \
    _Pragma("unroll") for (int k = 0; k < 4; k++) acc[i][j][k] = 0.0f;         \
    PROJ_ISSUE(smp, 0)                                                         \
    _Pragma("unroll 2")                                                        \
    for (int it = 0; it < 32; it++) {                                          \
        unsigned* Ws = smp + (it & 1) * PSTG;                                  \
        unsigned* Xs = Ws + 128 * WLD;                                         \
        __syncthreads();                                                       \
        if (it < 31) {                                                         \
            unsigned* nb = smp + ((it + 1) & 1) * PSTG;                        \
            PROJ_ISSUE(nb, (it + 1) * 16)                                      \
            cpwait<1>();                                                       \
        } else {                                                               \
            cpwait<0>();                                                       \
        }                                                                      \
        __syncthreads();                                                       \
        _Pragma("unroll")                                                      \
        for (int kk = 0; kk < 16; kk += 8) {                                   \
            unsigned afr[4][4];                                                \
            _Pragma("unroll") for (int tm = 0; tm < 4; tm++) {                 \
                const int row = wm + tm * 16;                                  \
                afr[tm][0] = Ws[(row + r) * WLD + kk + q];                     \
                afr[tm][1] = Ws[(row + r + 8) * WLD + kk + q];                 \
                afr[tm][2] = Ws[(row + r) * WLD + kk + q + 4];                 \
                afr[tm][3] = Ws[(row + r + 8) * WLD + kk + q + 4];             \
            }                                                                  \
            unsigned bfr[4][2];                                                \
            _Pragma("unroll") for (int tn = 0; tn < 4; tn++) {                 \
                const int col = wn + tn * 8 + r;                               \
                bfr[tn][0] = Xs[(kk + q) * XLD + col];                         \
                bfr[tn][1] = Xs[(kk + q + 4) * XLD + col];                     \
            }                                                                  \
            _Pragma("unroll") for (int tm = 0; tm < 4; tm++)                   \
            _Pragma("unroll") for (int tn = 0; tn < 4; tn++)                   \
                mma_tf32(acc[tm][tn], afr[tm], bfr[tn][0], bfr[tn][1]);        \
        }                                                                      \
    }

__global__ __launch_bounds__(256, 2) void qkv_gemm(const float* __restrict__ bias)
{
    __shared__ unsigned smp[2 * PSTG];

    const int tid = threadIdx.x;
    const int b = blockIdx.z, m0 = blockIdx.y * 128, n0 = blockIdx.x * 128;
    const int lane = tid & 31, warp = tid >> 5;
    const int q = lane & 3, r = lane >> 2;
    const int wm = (warp >> 2) * 64, wn = (warp & 3) * 32;
    const unsigned* Wg = g_Wqt + (size_t)m0 * CDIM;
    const unsigned* Xg = g_Xt + (size_t)b * CDIM * SEQ + n0;

    PROJ_MAINLOOP()

    const int which = m0 >> 9;
    unsigned* dst = (which == 0) ? g_Q : (which == 1) ? g_K : g_V;
    const float qs = (which == 0) ? 0.125f : 1.0f;

#pragma unroll
    for (int tm = 0; tm < 4; tm++) {
        const int mA = m0 + wm + tm * 16 + r;
        const int mB = mA + 8;
        const float bvA = bias[mA], bvB = bias[mB];
        unsigned* rowA = dst + ((size_t)b * CDIM + (mA & 511)) * SEQ;
        unsigned* rowB = dst + ((size_t)b * CDIM + (mB & 511)) * SEQ;
#pragma unroll
        for (int tn = 0; tn < 4; tn++) {
            const int n = n0 + wn + tn * 8 + 2 * q;
            *(uint2*)(rowA + n) = make_uint2(f2tf((acc[tm][tn][0] + bvA) * qs),
                                             f2tf((acc[tm][tn][1] + bvA) * qs));
            *(uint2*)(rowB + n) = make_uint2(f2tf((acc[tm][tn][2] + bvB) * qs),
                                             f2tf((acc[tm][tn][3] + bvB) * qs));
        }
    }
}

__global__ __launch_bounds__(256, 2) void out_gemm(const float* __restrict__ bias,
                                                   float* __restrict__ Y)
{
    __shared__ unsigned smp[2 * PSTG];

    const int tid = threadIdx.x;
    const int b = blockIdx.z, m0 = blockIdx.y * 128, n0 = blockIdx.x * 128;
    const int lane = tid & 31, warp = tid >> 5;
    const int q = lane & 3, r = lane >> 2;
    const int wm = (warp >> 2) * 64, wn = (warp & 3) * 32;
    const unsigned* Wg = g_Wot + (size_t)m0 * CDIM;
    const unsigned* Xg = g_O + (size_t)b * CDIM * SEQ + n0;

    PROJ_MAINLOOP()

#pragma unroll
    for (int tm = 0; tm < 4; tm++) {
        const int mA = m0 + wm + tm * 16 + r;
        const int mB = mA + 8;
        const float bvA = bias[mA], bvB = bias[mB];
        float* rowA = Y + ((size_t)b * CDIM + mA) * SEQ;
        float* rowB = Y + ((size_t)b * CDIM + mB) * SEQ;
#pragma unroll
        for (int tn = 0; tn < 4; tn++) {
            const int n = n0 + wn + tn * 8 + 2 * q;
            *(float2*)(rowA + n) = make_float2(acc[tm][tn][0] + bvA,
                                               acc[tm][tn][1] + bvA);
            *(float2*)(rowB + n) = make_float2(acc[tm][tn][2] + bvB,
                                               acc[tm][tn][3] + bvB);
        }
    }
}

// ---------------------------------------------------------------------------
// Flash attention. grid=(18, 32), 256 thr (8 warps), 2 CTAs/SM.
// Smem words: QP union(Qstage[64][136], P[128][68]) = 8704
//           | 2 stages x (Ks[64][72] + Vs[64][68]) = 2 x 8960  -> 104 KB
// ---------------------------------------------------------------------------
#define QLD 136
#define KLD 72
#define VLD 68
#define PST 68
#define OFF_K 8704
#define KVSTG 8960
#define FLASH_WORDS (OFF_K + 2 * KVSTG)    // 26624
#define FLASH_BYTES (FLASH_WORDS * 4)      // 106496

#define FLASH_ISSUE_KV(s_, t0_)                                                \
    {                                                                          \
        unsigned* Ksb = smw + OFF_K + (s_) * KVSTG;                            \
        unsigned* Vsb = Ksb + 64 * KLD;                                        \
        _Pragma("unroll") for (int j = 0; j < 4; j++) {                        \
            const int c = tid * 4 + j;                                         \
            const int dd = c >> 4, tc = (c & 15) * 4;                          \
            cp16(Ksb + dd * KLD + tc, Kg + (size_t)dd * SEQ + (t0_) + tc);     \
            cp16(Vsb + dd * VLD + tc, Vg + (size_t)dd * SEQ + (t0_) + tc);     \
        }                                                                      \
        cpcommit();                                                            \
    }

__global__ __launch_bounds__(256, 2) void flash_attn()
{
    extern __shared__ unsigned smw[];
    unsigned* QP = smw;   // Q staging, later P

    const int tid  = threadIdx.x;
    const int warp = tid >> 5, lane = tid & 31;
    const int q = lane & 3, r = lane >> 2;
    const int rw = warp * 16;
    const int bh = blockIdx.y;
    const int s0 = blockIdx.x * 128;

    const unsigned* Qg = g_Q + (size_t)bh * HD * SEQ;
    const unsigned* Kg = g_K + (size_t)bh * HD * SEQ;
    const unsigned* Vg = g_V + (size_t)bh * HD * SEQ;
    unsigned*       Og = g_O + (size_t)bh * HD * SEQ;

    // Q stage (group 0), first K/V stage (group 1)
#pragma unroll
    for (int j = 0; j < 8; j++) {
        const int c = tid * 8 + j;
        const int dd = c >> 5, sc = (c & 31) * 4;
        cp16(QP + dd * QLD + sc, Qg + (size_t)dd * SEQ + s0 + sc);
    }
    cpcommit();
    FLASH_ISSUE_KV(0, 0)
    cpwait<1>();          // Q staged (KV0 may still be in flight)
    __syncthreads();

    unsigned qa[8][4];
#pragma unroll
    for (int ks = 0; ks < 8; ks++) {
        qa[ks][0] = QP[(ks * 8 + q) * QLD + rw + r];
        qa[ks][1] = QP[(ks * 8 + q) * QLD + rw + r + 8];
        qa[ks][2] = QP[(ks * 8 + q + 4) * QLD + rw + r];
        qa[ks][3] = QP[(ks * 8 + q + 4) * QLD + rw + r + 8];
    }

    float O[8][4];
#pragma unroll
    for (int i = 0; i < 8; i++)
#pragma unroll
        for (int j = 0; j < 4; j++) O[i][j] = 0.0f;

    float mA = -1e30f, mB = -1e30f, lA = 0.0f, lB = 0.0f;

#pragma unroll 2
    for (int it = 0; it < 36; it++) {
        unsigned* Ks = smw + OFF_K + (it & 1) * KVSTG;
        unsigned* Vs = Ks + 64 * KLD;

        __syncthreads();   // A: stage (it+1)&1 fully consumed by tile it-1
        if (it < 35) {
            FLASH_ISSUE_KV((it + 1) & 1, (it + 1) * 64)
            cpwait<1>();
        } else {
            cpwait<0>();
        }
        __syncthreads();   // B: stage it&1 visible to all

        // S[16 warp rows][64 t] = Q . K
        float S[8][4];
#pragma unroll
        for (int tn = 0; tn < 8; tn++)
#pragma unroll
            for (int j = 0; j < 4; j++) S[tn][j] = 0.0f;

#pragma unroll
        for (int ks = 0; ks < 8; ks++) {
            const int k0 = ks * 8;
#pragma unroll
            for (int tn = 0; tn < 8; tn++) {
                unsigned b0 = Ks[(k0 + q) * KLD + tn * 8 + r];
                unsigned b1 = Ks[(k0 + q + 4) * KLD + tn * 8 + r];
                mma_tf32(S[tn], qa[ks], b0, b1);
            }
        }

        // online softmax in registers (rows rw+r and rw+r+8)
        float mxA = -1e30f, mxB = -1e30f;
#pragma unroll
        for (int tn = 0; tn < 8; tn++) {
            mxA = fmaxf(mxA, fmaxf(S[tn][0], S[tn][1]));
            mxB = fmaxf(mxB, fmaxf(S[tn][2], S[tn][3]));
        }
        mxA = fmaxf(mxA, __shfl_xor_sync(0xffffffffu, mxA, 1));
        mxA = fmaxf(mxA, __shfl_xor_sync(0xffffffffu, mxA, 2));
        mxB = fmaxf(mxB, __shfl_xor_sync(0xffffffffu, mxB, 1));
        mxB = fmaxf(mxB, __shfl_xor_sync(0xffffffffu, mxB, 2));

        const float mnA = fmaxf(mA, mxA), mnB = fmaxf(mB, mxB);
        const float cA = __expf(mA - mnA), cB = __expf(mB - mnB);
        float sA = 0.0f, sB = 0.0f;
#pragma unroll
        for (int tn = 0; tn < 8; tn++) {
            S[tn][0] = __expf(S[tn][0] - mnA); sA += S[tn][0];
            S[tn][1] = __expf(S[tn][1] - mnA); sA += S[tn][1];
            S[tn][2] = __expf(S[tn][2] - mnB); sB += S[tn][2];
            S[tn][3] = __expf(S[tn][3] - mnB); sB += S[tn][3];
        }
        sA += __shfl_xor_sync(0xffffffffu, sA, 1);
        sA += __shfl_xor_sync(0xffffffffu, sA, 2);
        sB += __shfl_xor_sync(0xffffffffu, sB, 1);
        sB += __shfl_xor_sync(0xffffffffu, sB, 2);

        lA = lA * cA + sA;  lB = lB * cB + sB;
        mA = mnA;           mB = mnB;
#pragma unroll
        for (int to = 0; to < 8; to++) {
            O[to][0] *= cA; O[to][1] *= cA;
            O[to][2] *= cB; O[to][3] *= cB;
        }

        // P into the freed Q-staging buffer (own warp rows only)
#pragma unroll
        for (int tn = 0; tn < 8; tn++) {
            const int t = tn * 8 + 2 * q;
            *(uint2*)&QP[(rw + r) * PST + t] =
                make_uint2(f2tf(S[tn][0]), f2tf(S[tn][1]));
            *(uint2*)&QP[(rw + r + 8) * PST + t] =
                make_uint2(f2tf(S[tn][2]), f2tf(S[tn][3]));
        }
        __syncwarp();   // PV reads only this warp's P rows

        // O[16 warp rows][64 d] += P . V
#pragma unroll
        for (int ks = 0; ks < 8; ks++) {
            const int k0 = ks * 8;
            unsigned a[4];
            a[0] = QP[(rw + r) * PST + k0 + q];
            a[1] = QP[(rw + r + 8) * PST + k0 + q];
            a[2] = QP[(rw + r) * PST + k0 + q + 4];
            a[3] = QP[(rw + r + 8) * PST + k0 + q + 4];
#pragma unroll
            for (int to = 0; to < 8; to++) {
                unsigned b0 = Vs[(to * 8 + r) * VLD + k0 + q];
                unsigned b1 = Vs[(to * 8 + r) * VLD + k0 + q + 4];
                mma_tf32(O[to], a, b0, b1);
            }
        }
    }

    // normalize + store O[b,h,d,s] as tf32 bits (consumed by out_gemm)
    const float iA = 1.0f / lA, iB = 1.0f / lB;
    const int sA0 = s0 + rw + r, sB0 = sA0 + 8;
#pragma unroll
    for (int to = 0; to < 8; to++) {
        const int d0 = to * 8 + 2 * q;
        Og[(size_t)d0 * SEQ + sA0]       = f2tf(O[to][0] * iA);
        Og[(size_t)(d0 + 1) * SEQ + sA0] = f2tf(O[to][1] * iA);
        Og[(size_t)d0 * SEQ + sB0]       = f2tf(O[to][2] * iB);
        Og[(size_t)(d0 + 1) * SEQ + sB0] = f2tf(O[to][3] * iB);
    }
}

// ---------------------------------------------------------------------------
extern "C" void kernel_launch(void* const* d_in, const int* in_sizes, int n_in,
                              void* d_out, int out_size)
{
    const float* x    = (const float*)d_in[0];
    const float* Wqkv = (const float*)d_in[1];
    const float* bqkv = (const float*)d_in[2];
    const float* Wout = (const float*)d_in[3];
    const float* bout = (const float*)d_in[4];
    float* out = (float*)d_out;

    cudaFuncSetAttribute(flash_attn, cudaFuncAttributeMaxDynamicSharedMemorySize,
                         FLASH_BYTES);

    prep<<<1184, 256>>>(x, Wqkv, Wout);
    qkv_gemm<<<dim3(SEQ / 128, MQKV / 128, BATCH), 256>>>(bqkv);
    flash_attn<<<dim3(SEQ / 128, BATCH * NH), 256, FLASH_BYTES>>>();
    out_gemm<<<dim3(SEQ / 128, CDIM / 128, BATCH), 256>>>(bout, out);
}

// round 8
// speedup vs baseline: 3.9779x; 1.1488x over previous
#include <cuda_runtime.h>

// ---------------------------------------------------------------------------
// MultiHeadSelfAttention, tf32 mma.sync + cp.async, fragment-order layouts.
//   prep      : x -> tf32 bits; Wqkv/Wout -> tf32 bits in A-FRAGMENT order
//               (each mma A-fragment = one LDS.128).
//   qkv_gemm  : 3-stage, one-barrier pipeline. Writes Q plain [bh,d,s] (tf32),
//               K pair-interleaved over d, V pair-interleaved over t, so flash
//               B-fragments are single LDS.64 loads.
//   flash_attn: 2-stage one-barrier pipeline, Q-frags in regs, K/V uint2
//               B-frags, P through smem (aliases Q staging). Writes O
//               pair-interleaved over k for out_gemm.
//   out_gemm  : 3-stage one-barrier pipeline, A = LDS.128, B = LDS.64.
// Pair-interleave word index within an 8-k slab: word(kin) = (kin&3)*2+(kin>>2)
// i.e. slot pair (q, q+4) sits at words (2q, 2q+1) — consistent everywhere.
// ---------------------------------------------------------------------------

#define BATCH 4
#define CDIM  512
#define SEQ   2304
#define NH    8
#define HD    64
#define MQKV  1536
#define SCR   (BATCH * CDIM * SEQ)

__device__ __align__(16) unsigned g_Q[SCR];   // [bh][d][s] plain tf32
__device__ __align__(16) unsigned g_K[SCR];   // ((bh*8+ks)*2304 + t)*8 + word(d%8)
__device__ __align__(16) unsigned g_V[SCR];   // (bh*64+d)*2304 + (t&~7)*?.. = row-linear, t perm within 8
__device__ __align__(16) unsigned g_O[SCR];   // ((b*64+ks)*2304 + s)*8 + word(k%8)
__device__ __align__(16) unsigned g_Xt[SCR];  // [b][c][s] plain tf32
__device__ __align__(16) unsigned g_Wq[MQKV * CDIM];  // A-fragment order
__device__ __align__(16) unsigned g_Wo[CDIM * CDIM];  // A-fragment order

__device__ __forceinline__ unsigned f2tf(float x) {
    unsigned r;
    asm("cvt.rna.tf32.f32 %0, %1;" : "=r"(r) : "f"(x));
    return r;
}

__device__ __forceinline__ void mma_tf32(float* c, const unsigned* a,
                                         unsigned b0, unsigned b1) {
    asm volatile(
        "mma.sync.aligned.m16n8k8.row.col.f32.tf32.tf32.f32 "
        "{%0,%1,%2,%3}, {%4,%5,%6,%7}, {%8,%9}, {%0,%1,%2,%3};"
        : "+f"(c[0]), "+f"(c[1]), "+f"(c[2]), "+f"(c[3])
        : "r"(a[0]), "r"(a[1]), "r"(a[2]), "r"(a[3]), "r"(b0), "r"(b1));
}

__device__ __forceinline__ void cp16(unsigned* dst, const unsigned* src) {
    unsigned da = (unsigned)__cvta_generic_to_shared(dst);
    asm volatile("cp.async.cg.shared.global [%0], [%1], 16;"
                 :: "r"(da), "l"(src));
}
__device__ __forceinline__ void cpcommit() {
    asm volatile("cp.async.commit_group;");
}
template <int N> __device__ __forceinline__ void cpwait() {
    asm volatile("cp.async.wait_group %0;" :: "n"(N));
}

// ---------------------------------------------------------------------------
// prep: x -> tf32 plain; W -> tf32 in A-fragment order:
// off(mb,ks,g,lane,w) = ((mb*64+ks)*8+g)*128 + lane*4 + w
//   m = mb*128 + g*16 + (w&1)*8 + (lane>>2),  k = ks*8 + (w>>1)*4 + (lane&3)
// ---------------------------------------------------------------------------
__global__ void prep(const float* __restrict__ x,
                     const float* __restrict__ Wqkv,
                     const float* __restrict__ Wout)
{
    const int stride = gridDim.x * blockDim.x;
    const int i0 = blockIdx.x * blockDim.x + threadIdx.x;
    for (int i = i0; i < SCR; i += stride) g_Xt[i] = f2tf(x[i]);
    for (int o = i0; o < MQKV * CDIM; o += stride) {
        const int w = o & 3, lane = (o >> 2) & 31, g = (o >> 7) & 7;
        const int ks = (o >> 10) & 63, mb = o >> 16;
        const int m = mb * 128 + g * 16 + (w & 1) * 8 + (lane >> 2);
        const int k = ks * 8 + (w >> 1) * 4 + (lane & 3);
        g_Wq[o] = f2tf(Wqkv[m * CDIM + k]);
    }
    for (int o = i0; o < CDIM * CDIM; o += stride) {
        const int w = o & 3, lane = (o >> 2) & 31, g = (o >> 7) & 7;
        const int ks = (o >> 10) & 63, mb = o >> 16;
        const int m = mb * 128 + g * 16 + (w & 1) * 8 + (lane >> 2);
        const int k = ks * 8 + (w >> 1) * 4 + (lane & 3);
        g_Wo[o] = f2tf(Wout[m * CDIM + k]);
    }
}

// ---------------------------------------------------------------------------
// qkv_gemm: 128x128 tile, BK=16, 3-stage one-barrier pipeline.
// Stage = Wfrag[2 slabs][8 g][128] (2048) + Xs[16][136] (2176) = 4224 words.
// ---------------------------------------------------------------------------
#define QKV_STG  4224
#define QKV_SMEM (3 * QKV_STG * 4)

#define QKV_ISSUE(s_, k0_) {                                                   \
    unsigned* st_ = smp + (s_) * QKV_STG;                                      \
    const unsigned* ws_ = Wg + ((k0_) >> 3) * 1024;                            \
    cp16(st_ + tid * 8,     ws_ + tid * 8);                                    \
    cp16(st_ + tid * 8 + 4, ws_ + tid * 8 + 4);                                \
    unsigned* xs_ = st_ + 2048;                                                \
    _Pragma("unroll") for (int j_ = 0; j_ < 2; j_++) {                         \
        const int c_ = tid * 2 + j_;                                           \
        const int kr_ = c_ >> 5, nc_ = (c_ & 31) * 4;                          \
        cp16(xs_ + kr_ * 136 + nc_, Xg + (size_t)((k0_) + kr_) * SEQ + nc_);   \
    }                                                                          \
    cpcommit(); }

__global__ __launch_bounds__(256, 2) void qkv_gemm(const float* __restrict__ bias)
{
    extern __shared__ unsigned smp[];
    const int tid = threadIdx.x;
    const int b = blockIdx.z, m0 = blockIdx.y * 128, n0 = blockIdx.x * 128;
    const int lane = tid & 31, warp = tid >> 5;
    const int q = lane & 3, r = lane >> 2;
    const int wm = (warp >> 2) * 64, wn = (warp & 3) * 32;
    const unsigned* Wg = g_Wq + (size_t)(m0 >> 7) * 65536;
    const unsigned* Xg = g_Xt + (size_t)b * CDIM * SEQ + n0;

    float acc[4][4][4];
#pragma unroll
    for (int i = 0; i < 4; i++)
#pragma unroll
        for (int j = 0; j < 4; j++)
#pragma unroll
            for (int k = 0; k < 4; k++) acc[i][j][k] = 0.0f;

    QKV_ISSUE(0, 0)
    QKV_ISSUE(1, 16)

    for (int it = 0; it < 32; it++) {
        if (it == 31) cpwait<0>(); else cpwait<1>();
        __syncthreads();
        if (it < 30) QKV_ISSUE((it + 2) % 3, (it + 2) * 16)
        unsigned* Ws = smp + (it % 3) * QKV_STG;
        unsigned* Xs = Ws + 2048;
#pragma unroll
        for (int kk = 0; kk < 16; kk += 8) {
            uint4 afr[4];
#pragma unroll
            for (int tm = 0; tm < 4; tm++)
                afr[tm] = *(const uint4*)&Ws[(kk >> 3) * 1024 +
                                             ((wm >> 4) + tm) * 128 + lane * 4];
            unsigned b0[4], b1[4];
#pragma unroll
            for (int tn = 0; tn < 4; tn++) {
                const int col = wn + tn * 8 + r;
                b0[tn] = Xs[(kk + q) * 136 + col];
                b1[tn] = Xs[(kk + q + 4) * 136 + col];
            }
#pragma unroll
            for (int tm = 0; tm < 4; tm++)
#pragma unroll
                for (int tn = 0; tn < 4; tn++)
                    mma_tf32(acc[tm][tn], (const unsigned*)&afr[tm], b0[tn], b1[tn]);
        }
    }

    const int which = m0 >> 9;
    if (which == 0) {
        // Q: plain [bh][d][s] as tf32 bits, pre-scaled by 0.125
#pragma unroll
        for (int tm = 0; tm < 4; tm++) {
            const int mA = m0 + wm + tm * 16 + r;
            const float bvA = bias[mA], bvB = bias[mA + 8];
            unsigned* rowA = g_Q + ((size_t)b * CDIM + (mA & 511)) * SEQ;
            unsigned* rowB = g_Q + ((size_t)b * CDIM + ((mA + 8) & 511)) * SEQ;
#pragma unroll
            for (int tn = 0; tn < 4; tn++) {
                const int n = n0 + wn + tn * 8 + 2 * q;
                *(uint2*)(rowA + n) = make_uint2(f2tf((acc[tm][tn][0] + bvA) * 0.125f),
                                                 f2tf((acc[tm][tn][1] + bvA) * 0.125f));
                *(uint2*)(rowB + n) = make_uint2(f2tf((acc[tm][tn][2] + bvB) * 0.125f),
                                                 f2tf((acc[tm][tn][3] + bvB) * 0.125f));
            }
        }
    } else if (which == 1) {
        // K: ((bh*8+ks)*2304 + t)*8 + word(d%8); d%8 == r here.
#pragma unroll
        for (int tm = 0; tm < 4; tm++) {
            const int mA = m0 + wm + tm * 16 + r;
            const int loc = mA & 511, h = loc >> 6, dA = loc & 63;
            const int bh = b * NH + h, ksA = dA >> 3;
            const int wA = (r & 3) * 2 + (r >> 2);
            const float bvA = bias[mA], bvB = bias[mA + 8];
            const size_t baseA = (size_t)(bh * 8 + ksA) * 18432 + wA;
            const size_t baseB = baseA + 18432;
#pragma unroll
            for (int tn = 0; tn < 4; tn++) {
                const int n = n0 + wn + tn * 8 + 2 * q;
                g_K[baseA + (size_t)n * 8]       = f2tf(acc[tm][tn][0] + bvA);
                g_K[baseA + (size_t)(n + 1) * 8] = f2tf(acc[tm][tn][1] + bvA);
                g_K[baseB + (size_t)n * 8]       = f2tf(acc[tm][tn][2] + bvB);
                g_K[baseB + (size_t)(n + 1) * 8] = f2tf(acc[tm][tn][3] + bvB);
            }
        }
    } else {
        // V: (bh*64+d)*2304 + (t&~7) + word(t%8)
        const int w0 = ((2 * q) & 3) * 2 + ((2 * q) >> 2);
        const int w1 = ((2 * q + 1) & 3) * 2 + ((2 * q + 1) >> 2);
#pragma unroll
        for (int tm = 0; tm < 4; tm++) {
            const int mA = m0 + wm + tm * 16 + r;
            const int loc = mA & 511, h = loc >> 6, dA = loc & 63;
            const int bh = b * NH + h;
            const float bvA = bias[mA], bvB = bias[mA + 8];
            const size_t bA = (size_t)(bh * 64 + dA) * 2304;
            const size_t bB = bA + 8 * 2304;
#pragma unroll
            for (int tn = 0; tn < 4; tn++) {
                const int ns = n0 + wn + tn * 8;   // n & ~7
                g_V[bA + ns + w0] = f2tf(acc[tm][tn][0] + bvA);
                g_V[bA + ns + w1] = f2tf(acc[tm][tn][1] + bvA);
                g_V[bB + ns + w0] = f2tf(acc[tm][tn][2] + bvB);
                g_V[bB + ns + w1] = f2tf(acc[tm][tn][3] + bvB);
            }
        }
    }
}

// ---------------------------------------------------------------------------
// out_gemm: like qkv but B comes from pair-interleaved g_O -> LDS.64 B-frags.
// Stage = Wfrag 2048 + Opair [2 slabs][128 n][8] 2048 = 4096 words.
// ---------------------------------------------------------------------------
#define OUT_STG  4096
#define OUT_SMEM (3 * OUT_STG * 4)

#define OUT_ISSUE(s_, k0_) {                                                   \
    unsigned* st_ = smp + (s_) * OUT_STG;                                      \
    const unsigned* ws_ = Wg + ((k0_) >> 3) * 1024;                            \
    cp16(st_ + tid * 8,     ws_ + tid * 8);                                    \
    cp16(st_ + tid * 8 + 4, ws_ + tid * 8 + 4);                                \
    unsigned* od_ = st_ + 2048 + (tid >> 7) * 1024 + (tid & 127) * 8;          \
    const unsigned* os_ = Og + ((size_t)((k0_) >> 3) + (tid >> 7)) * 18432     \
                             + (tid & 127) * 8;                                \
    cp16(od_, os_);                                                            \
    cp16(od_ + 4, os_ + 4);                                                    \
    cpcommit(); }

__global__ __launch_bounds__(256, 2) void out_gemm(const float* __restrict__ bias,
                                                   float* __restrict__ Y)
{
    extern __shared__ unsigned smp[];
    const int tid = threadIdx.x;
    const int b = blockIdx.z, m0 = blockIdx.y * 128, n0 = blockIdx.x * 128;
    const int lane = tid & 31, warp = tid >> 5;
    const int q = lane & 3, r = lane >> 2;
    const int wm = (warp >> 2) * 64, wn = (warp & 3) * 32;
    const unsigned* Wg = g_Wo + (size_t)(m0 >> 7) * 65536;
    const unsigned* Og = g_O + (size_t)b * 1179648 + (size_t)n0 * 8;

    float acc[4][4][4];
#pragma unroll
    for (int i = 0; i < 4; i++)
#pragma unroll
        for (int j = 0; j < 4; j++)
#pragma unroll
            for (int k = 0; k < 4; k++) acc[i][j][k] = 0.0f;

    OUT_ISSUE(0, 0)
    OUT_ISSUE(1, 16)

    for (int it = 0; it < 32; it++) {
        if (it == 31) cpwait<0>(); else cpwait<1>();
        __syncthreads();
        if (it < 30) OUT_ISSUE((it + 2) % 3, (it + 2) * 16)
        unsigned* Ws = smp + (it % 3) * OUT_STG;
        unsigned* Os = Ws + 2048;
#pragma unroll
        for (int kk = 0; kk < 16; kk += 8) {
            uint4 afr[4];
#pragma unroll
            for (int tm = 0; tm < 4; tm++)
                afr[tm] = *(const uint4*)&Ws[(kk >> 3) * 1024 +
                                             ((wm >> 4) + tm) * 128 + lane * 4];
            uint2 bfr[4];
#pragma unroll
            for (int tn = 0; tn < 4; tn++)
                bfr[tn] = *(const uint2*)&Os[(kk >> 3) * 1024 +
                                             (wn + tn * 8 + r) * 8 + q * 2];
#pragma unroll
            for (int tm = 0; tm < 4; tm++)
#pragma unroll
                for (int tn = 0; tn < 4; tn++)
                    mma_tf32(acc[tm][tn], (const unsigned*)&afr[tm],
                             bfr[tn].x, bfr[tn].y);
        }
    }

#pragma unroll
    for (int tm = 0; tm < 4; tm++) {
        const int mA = m0 + wm + tm * 16 + r;
        const float bvA = bias[mA], bvB = bias[mA + 8];
        float* rowA = Y + ((size_t)b * CDIM + mA) * SEQ;
        float* rowB = Y + ((size_t)b * CDIM + mA + 8) * SEQ;
#pragma unroll
        for (int tn = 0; tn < 4; tn++) {
            const int n = n0 + wn + tn * 8 + 2 * q;
            *(float2*)(rowA + n) = make_float2(acc[tm][tn][0] + bvA,
                                               acc[tm][tn][1] + bvA);
            *(float2*)(rowB + n) = make_float2(acc[tm][tn][2] + bvB,
                                               acc[tm][tn][3] + bvB);
        }
    }
}

// ---------------------------------------------------------------------------
// flash_attn: grid (18, 32), 256 thr, 2 CTAs/SM, one barrier per 64-key tile.
// Smem words: QP union(Qstage[64][136], P[128][68]) = 8704
//           | 2 stages x (K [8 slabs][64 t][8] 4096 + V [64 d][72] 4608)
// ---------------------------------------------------------------------------
#define QLD 136
#define PST 68
#define OFF_K 8704
#define KVSTG 8704
#define FLASH_WORDS (OFF_K + 2 * KVSTG)    // 26112
#define FLASH_BYTES (FLASH_WORDS * 4)      // 104448

#define FLASH_ISSUE_KV(s_, t0_) {                                              \
    unsigned* Ksb_ = smw + OFF_K + (s_) * KVSTG;                               \
    unsigned* Vsb_ = Ksb_ + 4096;                                              \
    _Pragma("unroll") for (int j_ = 0; j_ < 4; j_++) {                         \
        const int idx_ = tid * 16 + j_ * 4;                                    \
        const int ks_ = idx_ >> 9, rem_ = idx_ & 511;                          \
        cp16(Ksb_ + idx_, Kg + (size_t)ks_ * 18432 + (size_t)(t0_) * 8 + rem_);\
    }                                                                          \
    _Pragma("unroll") for (int j_ = 0; j_ < 4; j_++) {                         \
        const int ch_ = tid * 4 + j_;                                          \
        const int dd_ = ch_ >> 4, in_ = (ch_ & 15) * 4;                        \
        cp16(Vsb_ + dd_ * 72 + in_, Vg + (size_t)dd_ * 2304 + (t0_) + in_);    \
    }                                                                          \
    cpcommit(); }

__global__ __launch_bounds__(256, 2) void flash_attn()
{
    extern __shared__ unsigned smw[];
    unsigned* QP = smw;   // Q staging, later P

    const int tid  = threadIdx.x;
    const int warp = tid >> 5, lane = tid & 31;
    const int q = lane & 3, r = lane >> 2;
    const int rw = warp * 16;
    const int bh = blockIdx.y;
    const int s0 = blockIdx.x * 128;

    const unsigned* Qg = g_Q + (size_t)bh * 147456;
    const unsigned* Kg = g_K + (size_t)bh * 147456;
    const unsigned* Vg = g_V + (size_t)bh * 147456;

    // Q stage (group 0) + first K/V stage (group 1)
#pragma unroll
    for (int j = 0; j < 8; j++) {
        const int c = tid * 8 + j;
        const int dd = c >> 5, sc = (c & 31) * 4;
        cp16(QP + dd * QLD + sc, Qg + (size_t)dd * SEQ + s0 + sc);
    }
    cpcommit();
    FLASH_ISSUE_KV(0, 0)
    cpwait<1>();
    __syncthreads();

    unsigned qa[8][4];
#pragma unroll
    for (int ks = 0; ks < 8; ks++) {
        qa[ks][0] = QP[(ks * 8 + q) * QLD + rw + r];
        qa[ks][1] = QP[(ks * 8 + q) * QLD + rw + r + 8];
        qa[ks][2] = QP[(ks * 8 + q + 4) * QLD + rw + r];
        qa[ks][3] = QP[(ks * 8 + q + 4) * QLD + rw + r + 8];
    }

    float O[8][4];
#pragma unroll
    for (int i = 0; i < 8; i++)
#pragma unroll
        for (int j = 0; j < 4; j++) O[i][j] = 0.0f;

    float mA = -1e30f, mB = -1e30f, lA = 0.0f, lB = 0.0f;

    for (int it = 0; it < 36; it++) {
        cpwait<0>();
        __syncthreads();   // stage it ready everywhere; stage it-1 consumed
        if (it < 35) FLASH_ISSUE_KV((it + 1) & 1, (it + 1) * 64)
        unsigned* Ks = smw + OFF_K + (it & 1) * KVSTG;
        unsigned* Vs = Ks + 4096;

        // S[16 warp rows][64 t] = Q . K  (K B-frag = one LDS.64)
        float S[8][4];
#pragma unroll
        for (int tn = 0; tn < 8; tn++)
#pragma unroll
            for (int j = 0; j < 4; j++) S[tn][j] = 0.0f;

#pragma unroll
        for (int ks = 0; ks < 8; ks++)
#pragma unroll
            for (int tn = 0; tn < 8; tn++) {
                const uint2 kb = *(const uint2*)&Ks[ks * 512 + (tn * 8 + r) * 8 + q * 2];
                mma_tf32(S[tn], qa[ks], kb.x, kb.y);
            }

        // online softmax in registers (rows rw+r and rw+r+8)
        float mxA = -1e30f, mxB = -1e30f;
#pragma unroll
        for (int tn = 0; tn < 8; tn++) {
            mxA = fmaxf(mxA, fmaxf(S[tn][0], S[tn][1]));
            mxB = fmaxf(mxB, fmaxf(S[tn][2], S[tn][3]));
        }
        mxA = fmaxf(mxA, __shfl_xor_sync(0xffffffffu, mxA, 1));
        mxA = fmaxf(mxA, __shfl_xor_sync(0xffffffffu, mxA, 2));
        mxB = fmaxf(mxB, __shfl_xor_sync(0xffffffffu, mxB, 1));
        mxB = fmaxf(mxB, __shfl_xor_sync(0xffffffffu, mxB, 2));

        const float mnA = fmaxf(mA, mxA), mnB = fmaxf(mB, mxB);
        const float cA = __expf(mA - mnA), cB = __expf(mB - mnB);
        float sA = 0.0f, sB = 0.0f;
#pragma unroll
        for (int tn = 0; tn < 8; tn++) {
            S[tn][0] = __expf(S[tn][0] - mnA); sA += S[tn][0];
            S[tn][1] = __expf(S[tn][1] - mnA); sA += S[tn][1];
            S[tn][2] = __expf(S[tn][2] - mnB); sB += S[tn][2];
            S[tn][3] = __expf(S[tn][3] - mnB); sB += S[tn][3];
        }
        sA += __shfl_xor_sync(0xffffffffu, sA, 1);
        sA += __shfl_xor_sync(0xffffffffu, sA, 2);
        sB += __shfl_xor_sync(0xffffffffu, sB, 1);
        sB += __shfl_xor_sync(0xffffffffu, sB, 2);

        lA = lA * cA + sA;  lB = lB * cB + sB;
        mA = mnA;           mB = mnB;
#pragma unroll
        for (int to = 0; to < 8; to++) {
            O[to][0] *= cA; O[to][1] *= cA;
            O[to][2] *= cB; O[to][3] *= cB;
        }

        // P into Q-staging buffer (own warp rows only -> warp-local hazard)
#pragma unroll
        for (int tn = 0; tn < 8; tn++) {
            const int t = tn * 8 + 2 * q;
            *(uint2*)&QP[(rw + r) * PST + t] =
                make_uint2(f2tf(S[tn][0]), f2tf(S[tn][1]));
            *(uint2*)&QP[(rw + r + 8) * PST + t] =
                make_uint2(f2tf(S[tn][2]), f2tf(S[tn][3]));
        }
        __syncwarp();

        // O[16 warp rows][64 d] += P . V  (V B-frag = one LDS.64)
#pragma unroll
        for (int ks = 0; ks < 8; ks++) {
            const int k0 = ks * 8;
            unsigned a[4];
            a[0] = QP[(rw + r) * PST + k0 + q];
            a[1] = QP[(rw + r + 8) * PST + k0 + q];
            a[2] = QP[(rw + r) * PST + k0 + q + 4];
            a[3] = QP[(rw + r + 8) * PST + k0 + q + 4];
#pragma unroll
            for (int to = 0; to < 8; to++) {
                const uint2 vb = *(const uint2*)&Vs[(to * 8 + r) * 72 + k0 + q * 2];
                mma_tf32(O[to], a, vb.x, vb.y);
            }
        }
    }

    // normalize + store O pair-interleaved for out_gemm:
    // off = ((bh*8 + to)*2304 + s)*8 + word(d%8)
    const float iA = 1.0f / lA, iB = 1.0f / lB;
    const int sA0 = s0 + rw + r, sB0 = sA0 + 8;
    const int w0 = ((2 * q) & 3) * 2 + ((2 * q) >> 2);
    const int w1 = ((2 * q + 1) & 3) * 2 + ((2 * q + 1) >> 2);
#pragma unroll
    for (int to = 0; to < 8; to++) {
        const size_t base = (size_t)(bh * 8 + to) * 18432;
        g_O[base + (size_t)sA0 * 8 + w0] = f2tf(O[to][0] * iA);
        g_O[base + (size_t)sA0 * 8 + w1] = f2tf(O[to][1] * iA);
        g_O[base + (size_t)sB0 * 8 + w0] = f2tf(O[to][2] * iB);
        g_O[base + (size_t)sB0 * 8 + w1] = f2tf(O[to][3] * iB);
    }
}

// ---------------------------------------------------------------------------
extern "C" void kernel_launch(void* const* d_in, const int* in_sizes, int n_in,
                              void* d_out, int out_size)
{
    const float* x    = (const float*)d_in[0];
    const float* Wqkv = (const float*)d_in[1];
    const float* bqkv = (const float*)d_in[2];
    const float* Wout = (const float*)d_in[3];
    const float* bout = (const float*)d_in[4];
    float* out = (float*)d_out;

    cudaFuncSetAttribute(qkv_gemm,  cudaFuncAttributeMaxDynamicSharedMemorySize, QKV_SMEM);
    cudaFuncSetAttribute(out_gemm,  cudaFuncAttributeMaxDynamicSharedMemorySize, OUT_SMEM);
    cudaFuncSetAttribute(flash_attn, cudaFuncAttributeMaxDynamicSharedMemorySize, FLASH_BYTES);

    prep<<<1184, 256>>>(x, Wqkv, Wout);
    qkv_gemm<<<dim3(SEQ / 128, MQKV / 128, BATCH), 256, QKV_SMEM>>>(bqkv);
    flash_attn<<<dim3(SEQ / 128, BATCH * NH), 256, FLASH_BYTES>>>();
    out_gemm<<<dim3(SEQ / 128, CDIM / 128, BATCH), 256, OUT_SMEM>>>(bout, out);
}

// round 9
// speedup vs baseline: 4.0746x; 1.0243x over previous
#include <cuda_runtime.h>

// ---------------------------------------------------------------------------
// MultiHeadSelfAttention, tf32 mma.sync + cp.async, paired-slab layouts:
// every K/V/X/O B-operand fragment(-pair) is a single LDS.128 / LDS.64.
//   prep      : x -> tf32 pair-interleaved [b][ks][s][8]; W -> A-frag order.
//   qkv_gemm  : 3-stage one-barrier pipeline (A=LDS.128, B=LDS.64).
//               Q plain [bh,d,s]*0.125; K -> [bh][dp][t][16] paired records;
//               V -> [bh][tblk][tp][d][16] paired records.
//   flash_attn: K/V fragment PAIRS via LDS.128, Q-frags in regs, P through
//               smem, one barrier per 64-key tile, 2 CTAs/SM.
//   out_gemm  : unchanged R8 structure (O pair-interleaved from flash).
// Pair-interleave within an 8-k slab: word(kin) = (kin&3)*2 + (kin>>2).
// 16-word record for slab-pair: w = q*4 + j, j in {b0even,b1even,b0odd,b1odd}.
// ---------------------------------------------------------------------------

#define BATCH 4
#define CDIM  512
#define SEQ   2304
#define NH    8
#define HD    64
#define MQKV  1536
#define SCR   (BATCH * CDIM * SEQ)

__device__ __align__(16) unsigned g_Q[SCR];   // [bh][d][s] plain tf32
__device__ __align__(16) unsigned g_K[SCR];   // ((bh*4+dp)*2304 + t)*16 + w
__device__ __align__(16) unsigned g_V[SCR];   // (((bh*36+tblk)*4+tp)*64 + d)*16 + w
__device__ __align__(16) unsigned g_O[SCR];   // ((bh*8+ks)*2304 + s)*8 + word(k%8)
__device__ __align__(16) unsigned g_Xt[SCR];  // ((b*64+ks)*2304 + s)*8 + word(k%8)
__device__ __align__(16) unsigned g_Wq[MQKV * CDIM];  // A-fragment order
__device__ __align__(16) unsigned g_Wo[CDIM * CDIM];  // A-fragment order

__device__ __forceinline__ unsigned f2tf(float x) {
    unsigned r;
    asm("cvt.rna.tf32.f32 %0, %1;" : "=r"(r) : "f"(x));
    return r;
}

__device__ __forceinline__ void mma_tf32(float* c, const unsigned* a,
                                         unsigned b0, unsigned b1) {
    asm volatile(
        "mma.sync.aligned.m16n8k8.row.col.f32.tf32.tf32.f32 "
        "{%0,%1,%2,%3}, {%4,%5,%6,%7}, {%8,%9}, {%0,%1,%2,%3};"
        : "+f"(c[0]), "+f"(c[1]), "+f"(c[2]), "+f"(c[3])
        : "r"(a[0]), "r"(a[1]), "r"(a[2]), "r"(a[3]), "r"(b0), "r"(b1));
}

__device__ __forceinline__ void cp16(unsigned* dst, const unsigned* src) {
    unsigned da = (unsigned)__cvta_generic_to_shared(dst);
    asm volatile("cp.async.cg.shared.global [%0], [%1], 16;"
                 :: "r"(da), "l"(src));
}
__device__ __forceinline__ void cpcommit() {
    asm volatile("cp.async.commit_group;");
}
template <int N> __device__ __forceinline__ void cpwait() {
    asm volatile("cp.async.wait_group %0;" :: "n"(N));
}

// ---------------------------------------------------------------------------
// prep: x -> tf32 pair-interleaved; W -> tf32 A-fragment order.
// ---------------------------------------------------------------------------
__global__ void prep(const float* __restrict__ x,
                     const float* __restrict__ Wqkv,
                     const float* __restrict__ Wout)
{
    const int stride = gridDim.x * blockDim.x;
    const int i0 = blockIdx.x * blockDim.x + threadIdx.x;
    for (int o = i0; o < SCR; o += stride) {
        const int w = o & 7;
        const int idx = o >> 3;
        const int s = idx % 2304;
        const int t = idx / 2304;                 // b*64 + ks
        const int k = (t & 63) * 8 + (w >> 1) + (w & 1) * 4;
        const int b = t >> 6;
        g_Xt[o] = f2tf(x[((size_t)(b * 512 + k)) * 2304 + s]);
    }
    for (int o = i0; o < MQKV * CDIM; o += stride) {
        const int w = o & 3, lane = (o >> 2) & 31, g = (o >> 7) & 7;
        const int ks = (o >> 10) & 63, mb = o >> 16;
        const int m = mb * 128 + g * 16 + (w & 1) * 8 + (lane >> 2);
        const int k = ks * 8 + (w >> 1) * 4 + (lane & 3);
        g_Wq[o] = f2tf(Wqkv[m * CDIM + k]);
    }
    for (int o = i0; o < CDIM * CDIM; o += stride) {
        const int w = o & 3, lane = (o >> 2) & 31, g = (o >> 7) & 7;
        const int ks = (o >> 10) & 63, mb = o >> 16;
        const int m = mb * 128 + g * 16 + (w & 1) * 8 + (lane >> 2);
        const int k = ks * 8 + (w >> 1) * 4 + (lane & 3);
        g_Wo[o] = f2tf(Wout[m * CDIM + k]);
    }
}

// ---------------------------------------------------------------------------
// Shared projection mainloop: 128x128 tile, BK=16, 3-stage one-barrier.
// Stage = Wfrag [2 slabs][8 g][128] (2048) + B pair-interleaved
//         [2 slabs][128 n][8] (2048) = 4096 words.
// ---------------------------------------------------------------------------
#define PRJ_STG  4096
#define PRJ_SMEM (3 * PRJ_STG * 4)

#define PRJ_ISSUE(s_, k0_) {                                                   \
    unsigned* st_ = smp + (s_) * PRJ_STG;                                      \
    const unsigned* ws_ = Wg + ((k0_) >> 3) * 1024;                            \
    cp16(st_ + tid * 8,     ws_ + tid * 8);                                    \
    cp16(st_ + tid * 8 + 4, ws_ + tid * 8 + 4);                                \
    _Pragma("unroll") for (int j_ = 0; j_ < 2; j_++) {                         \
        const int c_ = tid * 2 + j_;                                           \
        const int sl_ = c_ >> 8, n_ = (c_ & 255) >> 1, h_ = (c_ & 1) * 4;      \
        cp16(st_ + 2048 + sl_ * 1024 + n_ * 8 + h_,                            \
             Xg + ((size_t)((k0_) >> 3) + sl_) * 18432 + n_ * 8 + h_);         \
    }                                                                          \
    cpcommit(); }

#define PRJ_MAINLOOP()                                                         \
    float acc[4][4][4];                                                        \
    _Pragma("unroll") for (int i = 0; i < 4; i++)                              \
    _Pragma("unroll") for (int j = 0; j < 4; j++)                              \
    _Pragma("unroll") for (int k = 0; k < 4; k++) acc[i][j][k] = 0.0f;         \
    PRJ_ISSUE(0, 0)                                                            \
    PRJ_ISSUE(1, 16)                                                           \
    for (int it = 0; it < 32; it++) {                                          \
        if (it == 31) cpwait<0>(); else cpwait<1>();                           \
        __syncthreads();                                                       \
        if (it < 30) PRJ_ISSUE((it + 2) % 3, (it + 2) * 16)                    \
        unsigned* Ws = smp + (it % 3) * PRJ_STG;                               \
        unsigned* Xs = Ws + 2048;                                              \
        _Pragma("unroll")                                                      \
        for (int kk = 0; kk < 16; kk += 8) {                                   \
            uint4 afr[4];                                                      \
            _Pragma("unroll") for (int tm = 0; tm < 4; tm++)                   \
                afr[tm] = *(const uint4*)&Ws[(kk >> 3) * 1024 +                \
                                             ((wm >> 4) + tm) * 128 + lane * 4];\
            uint2 bfr[4];                                                      \
            _Pragma("unroll") for (int tn = 0; tn < 4; tn++)                   \
                bfr[tn] = *(const uint2*)&Xs[(kk >> 3) * 1024 +                \
                                             (wn + tn * 8 + r) * 8 + q * 2];   \
            _Pragma("unroll") for (int tm = 0; tm < 4; tm++)                   \
            _Pragma("unroll") for (int tn = 0; tn < 4; tn++)                   \
                mma_tf32(acc[tm][tn], (const unsigned*)&afr[tm],               \
                         bfr[tn].x, bfr[tn].y);                                \
        }                                                                      \
    }

// ---------------------------------------------------------------------------
__global__ __launch_bounds__(256, 2) void qkv_gemm(const float* __restrict__ bias)
{
    extern __shared__ unsigned smp[];
    const int tid = threadIdx.x;
    const int b = blockIdx.z, m0 = blockIdx.y * 128, n0 = blockIdx.x * 128;
    const int lane = tid & 31, warp = tid >> 5;
    const int q = lane & 3, r = lane >> 2;
    const int wm = (warp >> 2) * 64, wn = (warp & 3) * 32;
    const unsigned* Wg = g_Wq + (size_t)(m0 >> 7) * 65536;
    const unsigned* Xg = g_Xt + (size_t)b * 1179648 + (size_t)n0 * 8;

    PRJ_MAINLOOP()

    const int which = m0 >> 9;
    if (which == 0) {
        // Q: plain [bh][d][s] tf32, pre-scaled 0.125
#pragma unroll
        for (int tm = 0; tm < 4; tm++) {
            const int mA = m0 + wm + tm * 16 + r;
            const float bvA = bias[mA], bvB = bias[mA + 8];
            unsigned* rowA = g_Q + ((size_t)b * CDIM + (mA & 511)) * SEQ;
            unsigned* rowB = g_Q + ((size_t)b * CDIM + ((mA + 8) & 511)) * SEQ;
#pragma unroll
            for (int tn = 0; tn < 4; tn++) {
                const int n = n0 + wn + tn * 8 + 2 * q;
                *(uint2*)(rowA + n) = make_uint2(f2tf((acc[tm][tn][0] + bvA) * 0.125f),
                                                 f2tf((acc[tm][tn][1] + bvA) * 0.125f));
                *(uint2*)(rowB + n) = make_uint2(f2tf((acc[tm][tn][2] + bvB) * 0.125f),
                                                 f2tf((acc[tm][tn][3] + bvB) * 0.125f));
            }
        }
    } else if (which == 1) {
        // K paired record: ((bh*4+dp)*2304 + t)*16 + w ; d = 16*dp + rem,
        // w = (rem&3)*4 + (rem>>2). Here rem(dA)=r -> wA; rem(dB)=r+8 -> wA+2.
#pragma unroll
        for (int tm = 0; tm < 4; tm++) {
            const int mA = m0 + wm + tm * 16 + r;
            const int loc = mA & 511, h = loc >> 6, dA = loc & 63;
            const int bh = b * NH + h;
            const int dp = dA >> 4;
            const int wA = (r & 3) * 4 + (r >> 2);
            const float bvA = bias[mA], bvB = bias[mA + 8];
            const size_t base = (size_t)(bh * 4 + dp) * 36864 + wA;
#pragma unroll
            for (int tn = 0; tn < 4; tn++) {
                const int n = n0 + wn + tn * 8 + 2 * q;
                g_K[base + (size_t)n * 16]           = f2tf(acc[tm][tn][0] + bvA);
                g_K[base + (size_t)(n + 1) * 16]     = f2tf(acc[tm][tn][1] + bvA);
                g_K[base + (size_t)n * 16 + 2]       = f2tf(acc[tm][tn][2] + bvB);
                g_K[base + (size_t)(n + 1) * 16 + 2] = f2tf(acc[tm][tn][3] + bvB);
            }
        }
    } else {
        // V paired record: (((bh*36+tblk)*4+tp)*64 + d)*16 + w(t),
        // w(t) = (t&3)*4 + ((t>>2)&3). t,t+1 share the same record block.
#pragma unroll
        for (int tm = 0; tm < 4; tm++) {
            const int mA = m0 + wm + tm * 16 + r;
            const int loc = mA & 511, h = loc >> 6, dA = loc & 63;
            const int bh = b * NH + h;
            const float bvA = bias[mA], bvB = bias[mA + 8];
#pragma unroll
            for (int tn = 0; tn < 4; tn++) {
                const int t = n0 + wn + tn * 8 + 2 * q;
                const int w0 = (t & 3) * 4 + ((t >> 2) & 3);
                const int w1 = ((t + 1) & 3) * 4 + ((t >> 2) & 3);
                const size_t blk = ((size_t)(bh * 36 + (t >> 6)) * 4 +
                                    ((t >> 4) & 3)) * 1024;
                g_V[blk + dA * 16 + w0]       = f2tf(acc[tm][tn][0] + bvA);
                g_V[blk + dA * 16 + w1]       = f2tf(acc[tm][tn][1] + bvA);
                g_V[blk + (dA + 8) * 16 + w0] = f2tf(acc[tm][tn][2] + bvB);
                g_V[blk + (dA + 8) * 16 + w1] = f2tf(acc[tm][tn][3] + bvB);
            }
        }
    }
}

// ---------------------------------------------------------------------------
__global__ __launch_bounds__(256, 2) void out_gemm(const float* __restrict__ bias,
                                                   float* __restrict__ Y)
{
    extern __shared__ unsigned smp[];
    const int tid = threadIdx.x;
    const int b = blockIdx.z, m0 = blockIdx.y * 128, n0 = blockIdx.x * 128;
    const int lane = tid & 31, warp = tid >> 5;
    const int q = lane & 3, r = lane >> 2;
    const int wm = (warp >> 2) * 64, wn = (warp & 3) * 32;
    const unsigned* Wg = g_Wo + (size_t)(m0 >> 7) * 65536;
    const unsigned* Xg = g_O + (size_t)b * 1179648 + (size_t)n0 * 8;

    PRJ_MAINLOOP()

#pragma unroll
    for (int tm = 0; tm < 4; tm++) {
        const int mA = m0 + wm + tm * 16 + r;
        const float bvA = bias[mA], bvB = bias[mA + 8];
        float* rowA = Y + ((size_t)b * CDIM + mA) * SEQ;
        float* rowB = Y + ((size_t)b * CDIM + mA + 8) * SEQ;
#pragma unroll
        for (int tn = 0; tn < 4; tn++) {
            const int n = n0 + wn + tn * 8 + 2 * q;
            *(float2*)(rowA + n) = make_float2(acc[tm][tn][0] + bvA,
                                               acc[tm][tn][1] + bvA);
            *(float2*)(rowB + n) = make_float2(acc[tm][tn][2] + bvB,
                                               acc[tm][tn][3] + bvB);
        }
    }
}

// ---------------------------------------------------------------------------
// flash_attn: grid (18, 32), 256 thr, 2 CTAs/SM, one barrier per 64-key tile.
// Smem words: QP union(Qstage[64][136], P[128][68]) = 8704
//           | 2 stages x (K [4 dp][64 t][16] + V [4 tp][64 d][16]) = 2 x 8192
// K/V fragment pairs are single LDS.128 (contiguous 512B per warp access).
// ---------------------------------------------------------------------------
#define QLD 136
#define PST 68
#define OFF_K 8704
#define KVSTG 8192
#define FLASH_WORDS (OFF_K + 2 * KVSTG)    // 25088
#define FLASH_BYTES (FLASH_WORDS * 4)      // 100352

#define FLASH_ISSUE_KV(s_, t0_) {                                              \
    unsigned* Ksb_ = smw + OFF_K + (s_) * KVSTG;                               \
    unsigned* Vsb_ = Ksb_ + 4096;                                              \
    _Pragma("unroll") for (int j_ = 0; j_ < 4; j_++) {                         \
        const int c_ = tid * 4 + j_;                                           \
        const int dp_ = c_ >> 8, tc_ = (c_ & 255) >> 2, w4_ = (c_ & 3) * 4;    \
        cp16(Ksb_ + dp_ * 1024 + tc_ * 16 + w4_,                               \
             Kg + (size_t)(dp_ * 2304 + (t0_) + tc_) * 16 + w4_);              \
    }                                                                          \
    _Pragma("unroll") for (int j_ = 0; j_ < 4; j_++) {                         \
        const int c_ = tid * 4 + j_;                                           \
        cp16(Vsb_ + c_ * 4, Vg + (size_t)((t0_) >> 6) * 4096 + c_ * 4);        \
    }                                                                          \
    cpcommit(); }

__global__ __launch_bounds__(256, 2) void flash_attn()
{
    extern __shared__ unsigned smw[];
    unsigned* QP = smw;   // Q staging, later P

    const int tid  = threadIdx.x;
    const int warp = tid >> 5, lane = tid & 31;
    const int q = lane & 3, r = lane >> 2;
    const int rw = warp * 16;
    const int bh = blockIdx.y;
    const int s0 = blockIdx.x * 128;

    const unsigned* Qg = g_Q + (size_t)bh * 147456;
    const unsigned* Kg = g_K + (size_t)bh * 147456;
    const unsigned* Vg = g_V + (size_t)bh * 147456;

    // Q stage (group 0) + first K/V stage (group 1)
#pragma unroll
    for (int j = 0; j < 8; j++) {
        const int c = tid * 8 + j;
        const int dd = c >> 5, sc = (c & 31) * 4;
        cp16(QP + dd * QLD + sc, Qg + (size_t)dd * SEQ + s0 + sc);
    }
    cpcommit();
    FLASH_ISSUE_KV(0, 0)
    cpwait<1>();
    __syncthreads();

    unsigned qa[8][4];
#pragma unroll
    for (int ks = 0; ks < 8; ks++) {
        qa[ks][0] = QP[(ks * 8 + q) * QLD + rw + r];
        qa[ks][1] = QP[(ks * 8 + q) * QLD + rw + r + 8];
        qa[ks][2] = QP[(ks * 8 + q + 4) * QLD + rw + r];
        qa[ks][3] = QP[(ks * 8 + q + 4) * QLD + rw + r + 8];
    }

    float O[8][4];
#pragma unroll
    for (int i = 0; i < 8; i++)
#pragma unroll
        for (int j = 0; j < 4; j++) O[i][j] = 0.0f;

    float mA = -1e30f, mB = -1e30f, lA = 0.0f, lB = 0.0f;

    for (int it = 0; it < 36; it++) {
        cpwait<0>();
        __syncthreads();   // stage it visible; stage it-1 consumed everywhere
        if (it < 35) FLASH_ISSUE_KV((it + 1) & 1, (it + 1) * 64)
        unsigned* Ks = smw + OFF_K + (it & 1) * KVSTG;
        unsigned* Vs = Ks + 4096;

        // S[16 warp rows][64 t] = Q . K  (K fragment PAIR = one LDS.128)
        float S[8][4];
#pragma unroll
        for (int tn = 0; tn < 8; tn++)
#pragma unroll
            for (int j = 0; j < 4; j++) S[tn][j] = 0.0f;

#pragma unroll
        for (int dp = 0; dp < 4; dp++)
#pragma unroll
            for (int tn = 0; tn < 8; tn++) {
                const uint4 kb = *(const uint4*)&Ks[dp * 1024 +
                                                    (tn * 8 + r) * 16 + q * 4];
                mma_tf32(S[tn], qa[2 * dp],     kb.x, kb.y);
                mma_tf32(S[tn], qa[2 * dp + 1], kb.z, kb.w);
            }

        // online softmax in registers (rows rw+r and rw+r+8)
        float mxA = -1e30f, mxB = -1e30f;
#pragma unroll
        for (int tn = 0; tn < 8; tn++) {
            mxA = fmaxf(mxA, fmaxf(S[tn][0], S[tn][1]));
            mxB = fmaxf(mxB, fmaxf(S[tn][2], S[tn][3]));
        }
        mxA = fmaxf(mxA, __shfl_xor_sync(0xffffffffu, mxA, 1));
        mxA = fmaxf(mxA, __shfl_xor_sync(0xffffffffu, mxA, 2));
        mxB = fmaxf(mxB, __shfl_xor_sync(0xffffffffu, mxB, 1));
        mxB = fmaxf(mxB, __shfl_xor_sync(0xffffffffu, mxB, 2));

        const float mnA = fmaxf(mA, mxA), mnB = fmaxf(mB, mxB);
        const float cA = __expf(mA - mnA), cB = __expf(mB - mnB);
        float sA = 0.0f, sB = 0.0f;
#pragma unroll
        for (int tn = 0; tn < 8; tn++) {
            S[tn][0] = __expf(S[tn][0] - mnA); sA += S[tn][0];
            S[tn][1] = __expf(S[tn][1] - mnA); sA += S[tn][1];
            S[tn][2] = __expf(S[tn][2] - mnB); sB += S[tn][2];
            S[tn][3] = __expf(S[tn][3] - mnB); sB += S[tn][3];
        }
        sA += __shfl_xor_sync(0xffffffffu, sA, 1);
        sA += __shfl_xor_sync(0xffffffffu, sA, 2);
        sB += __shfl_xor_sync(0xffffffffu, sB, 1);
        sB += __shfl_xor_sync(0xffffffffu, sB, 2);

        lA = lA * cA + sA;  lB = lB * cB + sB;
        mA = mnA;           mB = mnB;
#pragma unroll
        for (int to = 0; to < 8; to++) {
            O[to][0] *= cA; O[to][1] *= cA;
            O[to][2] *= cB; O[to][3] *= cB;
        }

        // P into Q-staging buffer (own warp rows only -> warp-local hazard)
#pragma unroll
        for (int tn = 0; tn < 8; tn++) {
            const int t = tn * 8 + 2 * q;
            *(uint2*)&QP[(rw + r) * PST + t] =
                make_uint2(f2tf(S[tn][0]), f2tf(S[tn][1]));
            *(uint2*)&QP[(rw + r + 8) * PST + t] =
                make_uint2(f2tf(S[tn][2]), f2tf(S[tn][3]));
        }
        __syncwarp();

        // O[16 warp rows][64 d] += P . V  (V fragment PAIR = one LDS.128)
#pragma unroll
        for (int tp = 0; tp < 4; tp++) {
            const int k0 = tp * 16;
            unsigned ae[4], ao[4];
            ae[0] = QP[(rw + r) * PST + k0 + q];
            ae[1] = QP[(rw + r + 8) * PST + k0 + q];
            ae[2] = QP[(rw + r) * PST + k0 + q + 4];
            ae[3] = QP[(rw + r + 8) * PST + k0 + q + 4];
            ao[0] = QP[(rw + r) * PST + k0 + 8 + q];
            ao[1] = QP[(rw + r + 8) * PST + k0 + 8 + q];
            ao[2] = QP[(rw + r) * PST + k0 + 8 + q + 4];
            ao[3] = QP[(rw + r + 8) * PST + k0 + 8 + q + 4];
#pragma unroll
            for (int to = 0; to < 8; to++) {
                const uint4 vb = *(const uint4*)&Vs[tp * 1024 +
                                                    (to * 8 + r) * 16 + q * 4];
                mma_tf32(O[to], ae, vb.x, vb.y);
                mma_tf32(O[to], ao, vb.z, vb.w);
            }
        }
    }

    // normalize + store O pair-interleaved for out_gemm
    const float iA = 1.0f / lA, iB = 1.0f / lB;
    const int sA0 = s0 + rw + r, sB0 = sA0 + 8;
    const int w0 = ((2 * q) & 3) * 2 + ((2 * q) >> 2);
    const int w1 = ((2 * q + 1) & 3) * 2 + ((2 * q + 1) >> 2);
    unsigned* Og = g_O + (size_t)bh * 147456;
#pragma unroll
    for (int to = 0; to < 8; to++) {
        const size_t base = (size_t)(bh & 7, to) * 0;   // (silence unused)
        const size_t rowb = (size_t)to * 18432;
        Og[rowb + (size_t)sA0 * 8 + w0] = f2tf(O[to][0] * iA);
        Og[rowb + (size_t)sA0 * 8 + w1] = f2tf(O[to][1] * iA);
        Og[rowb + (size_t)sB0 * 8 + w0] = f2tf(O[to][2] * iB);
        Og[rowb + (size_t)sB0 * 8 + w1] = f2tf(O[to][3] * iB);
    }
}

// ---------------------------------------------------------------------------
extern "C" void kernel_launch(void* const* d_in, const int* in_sizes, int n_in,
                              void* d_out, int out_size)
{
    const float* x    = (const float*)d_in[0];
    const float* Wqkv = (const float*)d_in[1];
    const float* bqkv = (const float*)d_in[2];
    const float* Wout = (const float*)d_in[3];
    const float* bout = (const float*)d_in[4];
    float* out = (float*)d_out;

    cudaFuncSetAttribute(qkv_gemm,  cudaFuncAttributeMaxDynamicSharedMemorySize, PRJ_SMEM);
    cudaFuncSetAttribute(out_gemm,  cudaFuncAttributeMaxDynamicSharedMemorySize, PRJ_SMEM);
    cudaFuncSetAttribute(flash_attn, cudaFuncAttributeMaxDynamicSharedMemorySize, FLASH_BYTES);

    prep<<<1184, 256>>>(x, Wqkv, Wout);
    qkv_gemm<<<dim3(SEQ / 128, MQKV / 128, BATCH), 256, PRJ_SMEM>>>(bqkv);
    flash_attn<<<dim3(SEQ / 128, BATCH * NH), 256, FLASH_BYTES>>>();
    out_gemm<<<dim3(SEQ / 128, CDIM / 128, BATCH), 256, PRJ_SMEM>>>(bout, out);
}

// round 10
// speedup vs baseline: 4.4154x; 1.0837x over previous
#include <cuda_runtime.h>

// ---------------------------------------------------------------------------
// MultiHeadSelfAttention, tf32 mma.sync + cp.async.
//   prep      : x -> tf32 pair-interleaved; W -> A-fragment order.
//   qkv_gemm  : BK=32, 3-stage one-barrier pipeline. Q plain*0.125;
//               K/V paired records for flash LDS.128 fragment pairs.
//   flash_attn: TWO INDEPENDENT 4-WARP GROUPS per CTA, each with private
//               32-key 2-stage ring + named barrier -> de-phased softmax/mma.
//   out_gemm  : BK=32, 3-stage pipeline on pair-interleaved O.
// All rounding points identical to R9 (rel_err canary: 6.101e-4).
// ---------------------------------------------------------------------------

#define BATCH 4
#define CDIM  512
#define SEQ   2304
#define NH    8
#define HD    64
#define MQKV  1536
#define SCR   (BATCH * CDIM * SEQ)

__device__ __align__(16) unsigned g_Q[SCR];   // [bh][d][s] plain tf32
__device__ __align__(16) unsigned g_K[SCR];   // ((bh*4+dp)*2304 + t)*16 + w
__device__ __align__(16) unsigned g_V[SCR];   // (((bh*36+tblk)*4+tp)*64 + d)*16 + w
__device__ __align__(16) unsigned g_O[SCR];   // ((bh*8+ks)*2304 + s)*8 + word(k%8)
__device__ __align__(16) unsigned g_Xt[SCR];  // ((b*64+ks)*2304 + s)*8 + word(k%8)
__device__ __align__(16) unsigned g_Wq[MQKV * CDIM];  // A-fragment order
__device__ __align__(16) unsigned g_Wo[CDIM * CDIM];  // A-fragment order

__device__ __forceinline__ unsigned f2tf(float x) {
    unsigned r;
    asm("cvt.rna.tf32.f32 %0, %1;" : "=r"(r) : "f"(x));
    return r;
}

__device__ __forceinline__ void mma_tf32(float* c, const unsigned* a,
                                         unsigned b0, unsigned b1) {
    asm volatile(
        "mma.sync.aligned.m16n8k8.row.col.f32.tf32.tf32.f32 "
        "{%0,%1,%2,%3}, {%4,%5,%6,%7}, {%8,%9}, {%0,%1,%2,%3};"
        : "+f"(c[0]), "+f"(c[1]), "+f"(c[2]), "+f"(c[3])
        : "r"(a[0]), "r"(a[1]), "r"(a[2]), "r"(a[3]), "r"(b0), "r"(b1));
}

__device__ __forceinline__ void cp16(unsigned* dst, const unsigned* src) {
    unsigned da = (unsigned)__cvta_generic_to_shared(dst);
    asm volatile("cp.async.cg.shared.global [%0], [%1], 16;"
                 :: "r"(da), "l"(src));
}
__device__ __forceinline__ void cpcommit() {
    asm volatile("cp.async.commit_group;");
}
template <int N> __device__ __forceinline__ void cpwait() {
    asm volatile("cp.async.wait_group %0;" :: "n"(N));
}

// ---------------------------------------------------------------------------
__global__ void prep(const float* __restrict__ x,
                     const float* __restrict__ Wqkv,
                     const float* __restrict__ Wout)
{
    const int stride = gridDim.x * blockDim.x;
    const int i0 = blockIdx.x * blockDim.x + threadIdx.x;
    for (int o = i0; o < SCR; o += stride) {
        const int w = o & 7;
        const int idx = o >> 3;
        const int s = idx % 2304;
        const int t = idx / 2304;                 // b*64 + ks
        const int k = (t & 63) * 8 + (w >> 1) + (w & 1) * 4;
        const int b = t >> 6;
        g_Xt[o] = f2tf(x[((size_t)(b * 512 + k)) * 2304 + s]);
    }
    for (int o = i0; o < MQKV * CDIM; o += stride) {
        const int w = o & 3, lane = (o >> 2) & 31, g = (o >> 7) & 7;
        const int ks = (o >> 10) & 63, mb = o >> 16;
        const int m = mb * 128 + g * 16 + (w & 1) * 8 + (lane >> 2);
        const int k = ks * 8 + (w >> 1) * 4 + (lane & 3);
        g_Wq[o] = f2tf(Wqkv[m * CDIM + k]);
    }
    for (int o = i0; o < CDIM * CDIM; o += stride) {
        const int w = o & 3, lane = (o >> 2) & 31, g = (o >> 7) & 7;
        const int ks = (o >> 10) & 63, mb = o >> 16;
        const int m = mb * 128 + g * 16 + (w & 1) * 8 + (lane >> 2);
        const int k = ks * 8 + (w >> 1) * 4 + (lane & 3);
        g_Wo[o] = f2tf(Wout[m * CDIM + k]);
    }
}

// ---------------------------------------------------------------------------
// Projection mainloop: 128x128 tile, BK=32, 3-stage one-barrier pipeline.
// Stage = Wfrag [4 slabs][8 g][128] (4096) + B pair-interleaved
//         [4 slabs][128 n][8] (4096) = 8192 words (32 KB); 3 stages = 96 KB.
// ---------------------------------------------------------------------------
#define PRJ_STG  8192
#define PRJ_SMEM (3 * PRJ_STG * 4)

#define PRJ_ISSUE(s_, k0_) {                                                   \
    unsigned* st_ = smp + (s_) * PRJ_STG;                                      \
    const unsigned* ws_ = Wg + ((k0_) >> 3) * 1024;                            \
    _Pragma("unroll") for (int j_ = 0; j_ < 4; j_++)                           \
        cp16(st_ + (tid * 4 + j_) * 4, ws_ + (tid * 4 + j_) * 4);              \
    _Pragma("unroll") for (int j_ = 0; j_ < 4; j_++) {                         \
        const int c_ = tid * 4 + j_;                                           \
        const int sl_ = c_ >> 8, n_ = (c_ & 255) >> 1, h_ = (c_ & 1) * 4;      \
        cp16(st_ + 4096 + sl_ * 1024 + n_ * 8 + h_,                            \
             Xg + ((size_t)((k0_) >> 3) + sl_) * 18432 + n_ * 8 + h_);         \
    }                                                                          \
    cpcommit(); }

#define PRJ_MAINLOOP()                                                         \
    float acc[4][4][4];                                                        \
    _Pragma("unroll") for (int i = 0; i < 4; i++)                              \
    _Pragma("unroll") for (int j = 0; j < 4; j++)                              \
    _Pragma("unroll") for (int k = 0; k < 4; k++) acc[i][j][k] = 0.0f;         \
    PRJ_ISSUE(0, 0)                                                            \
    PRJ_ISSUE(1, 32)                                                           \
    for (int it = 0; it < 16; it++) {                                          \
        if (it == 15) cpwait<0>(); else cpwait<1>();                           \
        __syncthreads();                                                       \
        if (it < 14) PRJ_ISSUE((it + 2) % 3, (it + 2) * 32)                    \
        unsigned* Ws = smp + (it % 3) * PRJ_STG;                               \
        unsigned* Xs = Ws + 4096;                                              \
        _Pragma("unroll")                                                      \
        for (int ss = 0; ss < 4; ss++) {                                       \
            uint4 afr[4];                                                      \
            _Pragma("unroll") for (int tm = 0; tm < 4; tm++)                   \
                afr[tm] = *(const uint4*)&Ws[ss * 1024 +                       \
                                             ((wm >> 4) + tm) * 128 + lane * 4];\
            uint2 bfr[4];                                                      \
            _Pragma("unroll") for (int tn = 0; tn < 4; tn++)                   \
                bfr[tn] = *(const uint2*)&Xs[ss * 1024 +                       \
                                             (wn + tn * 8 + r) * 8 + q * 2];   \
            _Pragma("unroll") for (int tm = 0; tm < 4; tm++)                   \
            _Pragma("unroll") for (int tn = 0; tn < 4; tn++)                   \
                mma_tf32(acc[tm][tn], (const unsigned*)&afr[tm],               \
                         bfr[tn].x, bfr[tn].y);                                \
        }                                                                      \
    }

// ---------------------------------------------------------------------------
__global__ __launch_bounds__(256, 2) void qkv_gemm(const float* __restrict__ bias)
{
    extern __shared__ unsigned smp[];
    const int tid = threadIdx.x;
    const int b = blockIdx.z, m0 = blockIdx.y * 128, n0 = blockIdx.x * 128;
    const int lane = tid & 31, warp = tid >> 5;
    const int q = lane & 3, r = lane >> 2;
    const int wm = (warp >> 2) * 64, wn = (warp & 3) * 32;
    const unsigned* Wg = g_Wq + (size_t)(m0 >> 7) * 65536;
    const unsigned* Xg = g_Xt + (size_t)b * 1179648 + (size_t)n0 * 8;

    PRJ_MAINLOOP()

    const int which = m0 >> 9;
    if (which == 0) {
#pragma unroll
        for (int tm = 0; tm < 4; tm++) {
            const int mA = m0 + wm + tm * 16 + r;
            const float bvA = bias[mA], bvB = bias[mA + 8];
            unsigned* rowA = g_Q + ((size_t)b * CDIM + (mA & 511)) * SEQ;
            unsigned* rowB = g_Q + ((size_t)b * CDIM + ((mA + 8) & 511)) * SEQ;
#pragma unroll
            for (int tn = 0; tn < 4; tn++) {
                const int n = n0 + wn + tn * 8 + 2 * q;
                *(uint2*)(rowA + n) = make_uint2(f2tf((acc[tm][tn][0] + bvA) * 0.125f),
                                                 f2tf((acc[tm][tn][1] + bvA) * 0.125f));
                *(uint2*)(rowB + n) = make_uint2(f2tf((acc[tm][tn][2] + bvB) * 0.125f),
                                                 f2tf((acc[tm][tn][3] + bvB) * 0.125f));
            }
        }
    } else if (which == 1) {
#pragma unroll
        for (int tm = 0; tm < 4; tm++) {
            const int mA = m0 + wm + tm * 16 + r;
            const int loc = mA & 511, h = loc >> 6, dA = loc & 63;
            const int bh = b * NH + h;
            const int dp = dA >> 4;
            const int wA = (r & 3) * 4 + (r >> 2);
            const float bvA = bias[mA], bvB = bias[mA + 8];
            const size_t base = (size_t)(bh * 4 + dp) * 36864 + wA;
#pragma unroll
            for (int tn = 0; tn < 4; tn++) {
                const int n = n0 + wn + tn * 8 + 2 * q;
                g_K[base + (size_t)n * 16]           = f2tf(acc[tm][tn][0] + bvA);
                g_K[base + (size_t)(n + 1) * 16]     = f2tf(acc[tm][tn][1] + bvA);
                g_K[base + (size_t)n * 16 + 2]       = f2tf(acc[tm][tn][2] + bvB);
                g_K[base + (size_t)(n + 1) * 16 + 2] = f2tf(acc[tm][tn][3] + bvB);
            }
        }
    } else {
#pragma unroll
        for (int tm = 0; tm < 4; tm++) {
            const int mA = m0 + wm + tm * 16 + r;
            const int loc = mA & 511, h = loc >> 6, dA = loc & 63;
            const int bh = b * NH + h;
            const float bvA = bias[mA], bvB = bias[mA + 8];
#pragma unroll
            for (int tn = 0; tn < 4; tn++) {
                const int t = n0 + wn + tn * 8 + 2 * q;
                const int w0 = (t & 3) * 4 + ((t >> 2) & 3);
                const int w1 = ((t + 1) & 3) * 4 + ((t >> 2) & 3);
                const size_t blk = ((size_t)(bh * 36 + (t >> 6)) * 4 +
                                    ((t >> 4) & 3)) * 1024;
                g_V[blk + dA * 16 + w0]       = f2tf(acc[tm][tn][0] + bvA);
                g_V[blk + dA * 16 + w1]       = f2tf(acc[tm][tn][1] + bvA);
                g_V[blk + (dA + 8) * 16 + w0] = f2tf(acc[tm][tn][2] + bvB);
                g_V[blk + (dA + 8) * 16 + w1] = f2tf(acc[tm][tn][3] + bvB);
            }
        }
    }
}

// ---------------------------------------------------------------------------
__global__ __launch_bounds__(256, 2) void out_gemm(const float* __restrict__ bias,
                                                   float* __restrict__ Y)
{
    extern __shared__ unsigned smp[];
    const int tid = threadIdx.x;
    const int b = blockIdx.z, m0 = blockIdx.y * 128, n0 = blockIdx.x * 128;
    const int lane = tid & 31, warp = tid >> 5;
    const int q = lane & 3, r = lane >> 2;
    const int wm = (warp >> 2) * 64, wn = (warp & 3) * 32;
    const unsigned* Wg = g_Wo + (size_t)(m0 >> 7) * 65536;
    const unsigned* Xg = g_O + (size_t)b * 1179648 + (size_t)n0 * 8;

    PRJ_MAINLOOP()

#pragma unroll
    for (int tm = 0; tm < 4; tm++) {
        const int mA = m0 + wm + tm * 16 + r;
        const float bvA = bias[mA], bvB = bias[mA + 8];
        float* rowA = Y + ((size_t)b * CDIM + mA) * SEQ;
        float* rowB = Y + ((size_t)b * CDIM + mA + 8) * SEQ;
#pragma unroll
        for (int tn = 0; tn < 4; tn++) {
            const int n = n0 + wn + tn * 8 + 2 * q;
            *(float2*)(rowA + n) = make_float2(acc[tm][tn][0] + bvA,
                                               acc[tm][tn][1] + bvA);
            *(float2*)(rowB + n) = make_float2(acc[tm][tn][2] + bvB,
                                               acc[tm][tn][3] + bvB);
        }
    }
}

// ---------------------------------------------------------------------------
// flash_attn: grid (18, 32), 256 thr, 2 CTAs/SM.
// Two INDEPENDENT 4-warp groups; group g owns q-rows [64g, 64g+64) and
// iterates all 72 32-key tiles with a private 2-stage ring + named barrier.
// Smem words: QP union(Qstage[64][136]=8704 ; P: grp0 [64][36] @0, grp1 @2304)
//           | ring: grp g @ 8704 + g*8192, stage s @ +s*4096
//             (K [4 dp][32 t][16] = 2048 | V [2 tp][64 d][16] = 2048)
// ---------------------------------------------------------------------------
#define QLD 136
#define PST 36
#define OFF_R 8704
#define FLASH_WORDS (OFF_R + 2 * 8192)     // 25088
#define FLASH_BYTES (FLASH_WORDS * 4)      // 100352

#define FLASH_ISSUE_KV(s_, t0_) {                                              \
    unsigned* st_ = ringg + (s_) * 4096;                                       \
    _Pragma("unroll") for (int j_ = 0; j_ < 4; j_++) {                         \
        const int c_ = tidg + j_ * 128;                                        \
        const int dp_ = c_ >> 7, tc_ = (c_ >> 2) & 31, w4_ = (c_ & 3) * 4;     \
        cp16(st_ + dp_ * 512 + tc_ * 16 + w4_,                                 \
             Kg + (size_t)(dp_ * 2304 + (t0_) + tc_) * 16 + w4_);              \
    }                                                                          \
    _Pragma("unroll") for (int j_ = 0; j_ < 4; j_++) {                         \
        const int c_ = tidg + j_ * 128;                                        \
        cp16(st_ + 2048 + c_ * 4, Vg + (size_t)((t0_) >> 4) * 1024 + c_ * 4);  \
    }                                                                          \
    cpcommit(); }

__global__ __launch_bounds__(256, 2) void flash_attn()
{
    extern __shared__ unsigned smw[];
    unsigned* QP = smw;   // Q staging, later per-group P

    const int tid  = threadIdx.x;
    const int warp = tid >> 5, lane = tid & 31;
    const int q = lane & 3, r = lane >> 2;
    const int g    = warp >> 2;            // group 0 / 1
    const int tidg = tid & 127;
    const int rw   = warp * 16;            // global q-row base (0..112)
    const int rwl  = (warp & 3) * 16;      // row base within group P
    unsigned* Pg   = QP + g * 2304;        // group P region
    unsigned* ringg = smw + OFF_R + g * 8192;
    const int bh = blockIdx.y;
    const int s0 = blockIdx.x * 128;

    const unsigned* Qg = g_Q + (size_t)bh * 147456;
    const unsigned* Kg = g_K + (size_t)bh * 147456;
    const unsigned* Vg = g_V + (size_t)bh * 147456;

    // Q stage (block-wide), then group g's tile 0.
#pragma unroll
    for (int j = 0; j < 8; j++) {
        const int c = tid * 8 + j;
        const int dd = c >> 5, sc = (c & 31) * 4;
        cp16(QP + dd * QLD + sc, Qg + (size_t)dd * SEQ + s0 + sc);
    }
    cpcommit();
    FLASH_ISSUE_KV(0, 0)
    cpwait<1>();          // Q staged
    __syncthreads();

    unsigned qa[8][4];
#pragma unroll
    for (int ks = 0; ks < 8; ks++) {
        qa[ks][0] = QP[(ks * 8 + q) * QLD + rw + r];
        qa[ks][1] = QP[(ks * 8 + q) * QLD + rw + r + 8];
        qa[ks][2] = QP[(ks * 8 + q + 4) * QLD + rw + r];
        qa[ks][3] = QP[(ks * 8 + q + 4) * QLD + rw + r + 8];
    }
    __syncthreads();      // ALL warps extracted Q before any P write reuses QP

    float O[8][4];
#pragma unroll
    for (int i = 0; i < 8; i++)
#pragma unroll
        for (int j = 0; j < 4; j++) O[i][j] = 0.0f;

    float mA = -1e30f, mB = -1e30f, lA = 0.0f, lB = 0.0f;

    for (int it = 0; it < 72; it++) {
        cpwait<0>();                               // group's tile it arrived
        asm volatile("bar.sync %0, 128;" :: "r"(g + 1) : "memory");
        if (it < 71) FLASH_ISSUE_KV((it + 1) & 1, (it + 1) * 32)
        unsigned* Ks = ringg + (it & 1) * 4096;
        unsigned* Vs = Ks + 2048;

        // S[16 warp rows][32 t] = Q . K  (K fragment PAIR = one LDS.128)
        float S[4][4];
#pragma unroll
        for (int tn = 0; tn < 4; tn++)
#pragma unroll
            for (int j = 0; j < 4; j++) S[tn][j] = 0.0f;

#pragma unroll
        for (int dp = 0; dp < 4; dp++)
#pragma unroll
            for (int tn = 0; tn < 4; tn++) {
                const uint4 kb = *(const uint4*)&Ks[dp * 512 +
                                                    (tn * 8 + r) * 16 + q * 4];
                mma_tf32(S[tn], qa[2 * dp],     kb.x, kb.y);
                mma_tf32(S[tn], qa[2 * dp + 1], kb.z, kb.w);
            }

        // online softmax (rows rw+r and rw+r+8)
        float mxA = -1e30f, mxB = -1e30f;
#pragma unroll
        for (int tn = 0; tn < 4; tn++) {
            mxA = fmaxf(mxA, fmaxf(S[tn][0], S[tn][1]));
            mxB = fmaxf(mxB, fmaxf(S[tn][2], S[tn][3]));
        }
        mxA = fmaxf(mxA, __shfl_xor_sync(0xffffffffu, mxA, 1));
        mxA = fmaxf(mxA, __shfl_xor_sync(0xffffffffu, mxA, 2));
        mxB = fmaxf(mxB, __shfl_xor_sync(0xffffffffu, mxB, 1));
        mxB = fmaxf(mxB, __shfl_xor_sync(0xffffffffu, mxB, 2));

        const float mnA = fmaxf(mA, mxA), mnB = fmaxf(mB, mxB);
        const float cA = __expf(mA - mnA), cB = __expf(mB - mnB);
        float sA = 0.0f, sB = 0.0f;
#pragma unroll
        for (int tn = 0; tn < 4; tn++) {
            S[tn][0] = __expf(S[tn][0] - mnA); sA += S[tn][0];
            S[tn][1] = __expf(S[tn][1] - mnA); sA += S[tn][1];
            S[tn][2] = __expf(S[tn][2] - mnB); sB += S[tn][2];
            S[tn][3] = __expf(S[tn][3] - mnB); sB += S[tn][3];
        }
        sA += __shfl_xor_sync(0xffffffffu, sA, 1);
        sA += __shfl_xor_sync(0xffffffffu, sA, 2);
        sB += __shfl_xor_sync(0xffffffffu, sB, 1);
        sB += __shfl_xor_sync(0xffffffffu, sB, 2);

        lA = lA * cA + sA;  lB = lB * cB + sB;
        mA = mnA;           mB = mnB;
#pragma unroll
        for (int to = 0; to < 8; to++) {
            O[to][0] *= cA; O[to][1] *= cA;
            O[to][2] *= cB; O[to][3] *= cB;
        }

        // P into group's region (own warp rows only -> warp-local hazard)
#pragma unroll
        for (int tn = 0; tn < 4; tn++) {
            const int t = tn * 8 + 2 * q;
            *(uint2*)&Pg[(rwl + r) * PST + t] =
                make_uint2(f2tf(S[tn][0]), f2tf(S[tn][1]));
            *(uint2*)&Pg[(rwl + r + 8) * PST + t] =
                make_uint2(f2tf(S[tn][2]), f2tf(S[tn][3]));
        }
        __syncwarp();

        // O[16 warp rows][64 d] += P . V  (V fragment PAIR = one LDS.128)
#pragma unroll
        for (int tp = 0; tp < 2; tp++) {
            const int k0 = tp * 16;
            unsigned ae[4], ao[4];
            ae[0] = Pg[(rwl + r) * PST + k0 + q];
            ae[1] = Pg[(rwl + r + 8) * PST + k0 + q];
            ae[2] = Pg[(rwl + r) * PST + k0 + q + 4];
            ae[3] = Pg[(rwl + r + 8) * PST + k0 + q + 4];
            ao[0] = Pg[(rwl + r) * PST + k0 + 8 + q];
            ao[1] = Pg[(rwl + r + 8) * PST + k0 + 8 + q];
            ao[2] = Pg[(rwl + r) * PST + k0 + 8 + q + 4];
            ao[3] = Pg[(rwl + r + 8) * PST + k0 + 8 + q + 4];
#pragma unroll
            for (int to = 0; to < 8; to++) {
                const uint4 vb = *(const uint4*)&Vs[tp * 1024 +
                                                    (to * 8 + r) * 16 + q * 4];
                mma_tf32(O[to], ae, vb.x, vb.y);
                mma_tf32(O[to], ao, vb.z, vb.w);
            }
        }
    }

    // normalize + store O pair-interleaved for out_gemm
    const float iA = 1.0f / lA, iB = 1.0f / lB;
    const int sA0 = s0 + rw + r, sB0 = sA0 + 8;
    const int w0 = ((2 * q) & 3) * 2 + ((2 * q) >> 2);
    const int w1 = ((2 * q + 1) & 3) * 2 + ((2 * q + 1) >> 2);
    unsigned* Og = g_O + (size_t)bh * 147456;
#pragma unroll
    for (int to = 0; to < 8; to++) {
        const size_t rowb = (size_t)to * 18432;
        Og[rowb + (size_t)sA0 * 8 + w0] = f2tf(O[to][0] * iA);
        Og[rowb + (size_t)sA0 * 8 + w1] = f2tf(O[to][1] * iA);
        Og[rowb + (size_t)sB0 * 8 + w0] = f2tf(O[to][2] * iB);
        Og[rowb + (size_t)sB0 * 8 + w1] = f2tf(O[to][3] * iB);
    }
}

// ---------------------------------------------------------------------------
extern "C" void kernel_launch(void* const* d_in, const int* in_sizes, int n_in,
                              void* d_out, int out_size)
{
    const float* x    = (const float*)d_in[0];
    const float* Wqkv = (const float*)d_in[1];
    const float* bqkv = (const float*)d_in[2];
    const float* Wout = (const float*)d_in[3];
    const float* bout = (const float*)d_in[4];
    float* out = (float*)d_out;

    cudaFuncSetAttribute(qkv_gemm,  cudaFuncAttributeMaxDynamicSharedMemorySize, PRJ_SMEM);
    cudaFuncSetAttribute(out_gemm,  cudaFuncAttributeMaxDynamicSharedMemorySize, PRJ_SMEM);
    cudaFuncSetAttribute(flash_attn, cudaFuncAttributeMaxDynamicSharedMemorySize, FLASH_BYTES);

    prep<<<1184, 256>>>(x, Wqkv, Wout);
    qkv_gemm<<<dim3(SEQ / 128, MQKV / 128, BATCH), 256, PRJ_SMEM>>>(bqkv);
    flash_attn<<<dim3(SEQ / 128, BATCH * NH), 256, FLASH_BYTES>>>();
    out_gemm<<<dim3(SEQ / 128, CDIM / 128, BATCH), 256, PRJ_SMEM>>>(bout, out);
}

// round 11
// speedup vs baseline: 4.6816x; 1.0603x over previous
#include <cuda_runtime.h>

// ---------------------------------------------------------------------------
// MultiHeadSelfAttention, tf32 mma.sync + cp.async.
//   prep      : x -> tf32 pair-interleaved; W -> A-fragment order.
//   qkv_gemm  : BK=16, FOUR-stage one-barrier pipeline (wait_group 2).
//               Q plain*0.125; K/V paired records for flash LDS.128 pairs.
//   flash_attn: two independent 4-warp groups per CTA, private 32-key
//               2-stage rings + named barriers (unchanged from R10).
//   out_gemm  : BK=16, four-stage pipeline on pair-interleaved O.
// ---------------------------------------------------------------------------

#define BATCH 4
#define CDIM  512
#define SEQ   2304
#define NH    8
#define HD    64
#define MQKV  1536
#define SCR   (BATCH * CDIM * SEQ)

__device__ __align__(16) unsigned g_Q[SCR];   // [bh][d][s] plain tf32
__device__ __align__(16) unsigned g_K[SCR];   // ((bh*4+dp)*2304 + t)*16 + w
__device__ __align__(16) unsigned g_V[SCR];   // (((bh*36+tblk)*4+tp)*64 + d)*16 + w
__device__ __align__(16) unsigned g_O[SCR];   // ((bh*8+ks)*2304 + s)*8 + word(k%8)
__device__ __align__(16) unsigned g_Xt[SCR];  // ((b*64+ks)*2304 + s)*8 + word(k%8)
__device__ __align__(16) unsigned g_Wq[MQKV * CDIM];  // A-fragment order
__device__ __align__(16) unsigned g_Wo[CDIM * CDIM];  // A-fragment order

__device__ __forceinline__ unsigned f2tf(float x) {
    unsigned r;
    asm("cvt.rna.tf32.f32 %0, %1;" : "=r"(r) : "f"(x));
    return r;
}

__device__ __forceinline__ void mma_tf32(float* c, const unsigned* a,
                                         unsigned b0, unsigned b1) {
    asm volatile(
        "mma.sync.aligned.m16n8k8.row.col.f32.tf32.tf32.f32 "
        "{%0,%1,%2,%3}, {%4,%5,%6,%7}, {%8,%9}, {%0,%1,%2,%3};"
        : "+f"(c[0]), "+f"(c[1]), "+f"(c[2]), "+f"(c[3])
        : "r"(a[0]), "r"(a[1]), "r"(a[2]), "r"(a[3]), "r"(b0), "r"(b1));
}

__device__ __forceinline__ void cp16(unsigned* dst, const unsigned* src) {
    unsigned da = (unsigned)__cvta_generic_to_shared(dst);
    asm volatile("cp.async.cg.shared.global [%0], [%1], 16;"
                 :: "r"(da), "l"(src));
}
__device__ __forceinline__ void cpcommit() {
    asm volatile("cp.async.commit_group;");
}
template <int N> __device__ __forceinline__ void cpwait() {
    asm volatile("cp.async.wait_group %0;" :: "n"(N));
}

// ---------------------------------------------------------------------------
__global__ void prep(const float* __restrict__ x,
                     const float* __restrict__ Wqkv,
                     const float* __restrict__ Wout)
{
    const int stride = gridDim.x * blockDim.x;
    const int i0 = blockIdx.x * blockDim.x + threadIdx.x;
    for (int o = i0; o < SCR; o += stride) {
        const int w = o & 7;
        const int idx = o >> 3;
        const int s = idx % 2304;
        const int t = idx / 2304;                 // b*64 + ks
        const int k = (t & 63) * 8 + (w >> 1) + (w & 1) * 4;
        const int b = t >> 6;
        g_Xt[o] = f2tf(x[((size_t)(b * 512 + k)) * 2304 + s]);
    }
    for (int o = i0; o < MQKV * CDIM; o += stride) {
        const int w = o & 3, lane = (o >> 2) & 31, g = (o >> 7) & 7;
        const int ks = (o >> 10) & 63, mb = o >> 16;
        const int m = mb * 128 + g * 16 + (w & 1) * 8 + (lane >> 2);
        const int k = ks * 8 + (w >> 1) * 4 + (lane & 3);
        g_Wq[o] = f2tf(Wqkv[m * CDIM + k]);
    }
    for (int o = i0; o < CDIM * CDIM; o += stride) {
        const int w = o & 3, lane = (o >> 2) & 31, g = (o >> 7) & 7;
        const int ks = (o >> 10) & 63, mb = o >> 16;
        const int m = mb * 128 + g * 16 + (w & 1) * 8 + (lane >> 2);
        const int k = ks * 8 + (w >> 1) * 4 + (lane & 3);
        g_Wo[o] = f2tf(Wout[m * CDIM + k]);
    }
}

// ---------------------------------------------------------------------------
// Projection mainloop: 128x128 tile, BK=16, FOUR-stage one-barrier pipeline.
// Stage = Wfrag [2 slabs][8 g][128] (2048) + B pair-interleaved
//         [2 slabs][128 n][8] (2048) = 4096 words (16 KB); 4 stages = 64 KB.
// wait_group 2 keeps two tiles of load slack in flight.
// ---------------------------------------------------------------------------
#define PRJ_STG  4096
#define PRJ_SMEM (4 * PRJ_STG * 4)

#define PRJ_ISSUE(s_, k0_) {                                                   \
    unsigned* st_ = smp + (s_) * PRJ_STG;                                      \
    const unsigned* ws_ = Wg + ((k0_) >> 3) * 1024;                            \
    cp16(st_ + tid * 8,     ws_ + tid * 8);                                    \
    cp16(st_ + tid * 8 + 4, ws_ + tid * 8 + 4);                                \
    _Pragma("unroll") for (int j_ = 0; j_ < 2; j_++) {                         \
        const int c_ = tid * 2 + j_;                                           \
        const int sl_ = c_ >> 8, n_ = (c_ & 255) >> 1, h_ = (c_ & 1) * 4;      \
        cp16(st_ + 2048 + sl_ * 1024 + n_ * 8 + h_,                            \
             Xg + ((size_t)((k0_) >> 3) + sl_) * 18432 + n_ * 8 + h_);         \
    }                                                                          \
    cpcommit(); }

#define PRJ_MAINLOOP()                                                         \
    float acc[4][4][4];                                                        \
    _Pragma("unroll") for (int i = 0; i < 4; i++)                              \
    _Pragma("unroll") for (int j = 0; j < 4; j++)                              \
    _Pragma("unroll") for (int k = 0; k < 4; k++) acc[i][j][k] = 0.0f;         \
    PRJ_ISSUE(0, 0)                                                            \
    PRJ_ISSUE(1, 16)                                                           \
    PRJ_ISSUE(2, 32)                                                           \
    for (int it = 0; it < 32; it++) {                                          \
        if (it == 31) cpwait<0>();                                             \
        else if (it == 30) cpwait<1>();                                        \
        else cpwait<2>();                                                      \
        __syncthreads();                                                       \
        if (it < 29) PRJ_ISSUE((it + 3) & 3, (it + 3) * 16)                    \
        unsigned* Ws = smp + (it & 3) * PRJ_STG;                               \
        unsigned* Xs = Ws + 2048;                                              \
        _Pragma("unroll")                                                      \
        for (int ss = 0; ss < 2; ss++) {                                       \
            uint4 afr[4];                                                      \
            _Pragma("unroll") for (int tm = 0; tm < 4; tm++)                   \
                afr[tm] = *(const uint4*)&Ws[ss * 1024 +                       \
                                             ((wm >> 4) + tm) * 128 + lane * 4];\
            uint2 bfr[4];                                                      \
            _Pragma("unroll") for (int tn = 0; tn < 4; tn++)                   \
                bfr[tn] = *(const uint2*)&Xs[ss * 1024 +                       \
                                             (wn + tn * 8 + r) * 8 + q * 2];   \
            _Pragma("unroll") for (int tm = 0; tm < 4; tm++)                   \
            _Pragma("unroll") for (int tn = 0; tn < 4; tn++)                   \
                mma_tf32(acc[tm][tn], (const unsigned*)&afr[tm],               \
                         bfr[tn].x, bfr[tn].y);                                \
        }                                                                      \
    }

// ---------------------------------------------------------------------------
__global__ __launch_bounds__(256, 2) void qkv_gemm(const float* __restrict__ bias)
{
    extern __shared__ unsigned smp[];
    const int tid = threadIdx.x;
    const int b = blockIdx.z, m0 = blockIdx.y * 128, n0 = blockIdx.x * 128;
    const int lane = tid & 31, warp = tid >> 5;
    const int q = lane & 3, r = lane >> 2;
    const int wm = (warp >> 2) * 64, wn = (warp & 3) * 32;
    const unsigned* Wg = g_Wq + (size_t)(m0 >> 7) * 65536;
    const unsigned* Xg = g_Xt + (size_t)b * 1179648 + (size_t)n0 * 8;

    PRJ_MAINLOOP()

    const int which = m0 >> 9;
    if (which == 0) {
#pragma unroll
        for (int tm = 0; tm < 4; tm++) {
            const int mA = m0 + wm + tm * 16 + r;
            const float bvA = bias[mA], bvB = bias[mA + 8];
            unsigned* rowA = g_Q + ((size_t)b * CDIM + (mA & 511)) * SEQ;
            unsigned* rowB = g_Q + ((size_t)b * CDIM + ((mA + 8) & 511)) * SEQ;
#pragma unroll
            for (int tn = 0; tn < 4; tn++) {
                const int n = n0 + wn + tn * 8 + 2 * q;
                *(uint2*)(rowA + n) = make_uint2(f2tf((acc[tm][tn][0] + bvA) * 0.125f),
                                                 f2tf((acc[tm][tn][1] + bvA) * 0.125f));
                *(uint2*)(rowB + n) = make_uint2(f2tf((acc[tm][tn][2] + bvB) * 0.125f),
                                                 f2tf((acc[tm][tn][3] + bvB) * 0.125f));
            }
        }
    } else if (which == 1) {
#pragma unroll
        for (int tm = 0; tm < 4; tm++) {
            const int mA = m0 + wm + tm * 16 + r;
            const int loc = mA & 511, h = loc >> 6, dA = loc & 63;
            const int bh = b * NH + h;
            const int dp = dA >> 4;
            const int wA = (r & 3) * 4 + (r >> 2);
            const float bvA = bias[mA], bvB = bias[mA + 8];
            const size_t base = (size_t)(bh * 4 + dp) * 36864 + wA;
#pragma unroll
            for (int tn = 0; tn < 4; tn++) {
                const int n = n0 + wn + tn * 8 + 2 * q;
                g_K[base + (size_t)n * 16]           = f2tf(acc[tm][tn][0] + bvA);
                g_K[base + (size_t)(n + 1) * 16]     = f2tf(acc[tm][tn][1] + bvA);
                g_K[base + (size_t)n * 16 + 2]       = f2tf(acc[tm][tn][2] + bvB);
                g_K[base + (size_t)(n + 1) * 16 + 2] = f2tf(acc[tm][tn][3] + bvB);
            }
        }
    } else {
#pragma unroll
        for (int tm = 0; tm < 4; tm++) {
            const int mA = m0 + wm + tm * 16 + r;
            const int loc = mA & 511, h = loc >> 6, dA = loc & 63;
            const int bh = b * NH + h;
            const float bvA = bias[mA], bvB = bias[mA + 8];
#pragma unroll
            for (int tn = 0; tn < 4; tn++) {
                const int t = n0 + wn + tn * 8 + 2 * q;
                const int w0 = (t & 3) * 4 + ((t >> 2) & 3);
                const int w1 = ((t + 1) & 3) * 4 + ((t >> 2) & 3);
                const size_t blk = ((size_t)(bh * 36 + (t >> 6)) * 4 +
                                    ((t >> 4) & 3)) * 1024;
                g_V[blk + dA * 16 + w0]       = f2tf(acc[tm][tn][0] + bvA);
                g_V[blk + dA * 16 + w1]       = f2tf(acc[tm][tn][1] + bvA);
                g_V[blk + (dA + 8) * 16 + w0] = f2tf(acc[tm][tn][2] + bvB);
                g_V[blk + (dA + 8) * 16 + w1] = f2tf(acc[tm][tn][3] + bvB);
            }
        }
    }
}

// ---------------------------------------------------------------------------
__global__ __launch_bounds__(256, 2) void out_gemm(const float* __restrict__ bias,
                                                   float* __restrict__ Y)
{
    extern __shared__ unsigned smp[];
    const int tid = threadIdx.x;
    const int b = blockIdx.z, m0 = blockIdx.y * 128, n0 = blockIdx.x * 128;
    const int lane = tid & 31, warp = tid >> 5;
    const int q = lane & 3, r = lane >> 2;
    const int wm = (warp >> 2) * 64, wn = (warp & 3) * 32;
    const unsigned* Wg = g_Wo + (size_t)(m0 >> 7) * 65536;
    const unsigned* Xg = g_O + (size_t)b * 1179648 + (size_t)n0 * 8;

    PRJ_MAINLOOP()

#pragma unroll
    for (int tm = 0; tm < 4; tm++) {
        const int mA = m0 + wm + tm * 16 + r;
        const float bvA = bias[mA], bvB = bias[mA + 8];
        float* rowA = Y + ((size_t)b * CDIM + mA) * SEQ;
        float* rowB = Y + ((size_t)b * CDIM + mA + 8) * SEQ;
#pragma unroll
        for (int tn = 0; tn < 4; tn++) {
            const int n = n0 + wn + tn * 8 + 2 * q;
            *(float2*)(rowA + n) = make_float2(acc[tm][tn][0] + bvA,
                                               acc[tm][tn][1] + bvA);
            *(float2*)(rowB + n) = make_float2(acc[tm][tn][2] + bvB,
                                               acc[tm][tn][3] + bvB);
        }
    }
}

// ---------------------------------------------------------------------------
// flash_attn (unchanged from R10): two independent 4-warp groups, private
// 32-key 2-stage rings, named barriers.
// ---------------------------------------------------------------------------
#define QLD 136
#define PST 36
#define OFF_R 8704
#define FLASH_WORDS (OFF_R + 2 * 8192)     // 25088
#define FLASH_BYTES (FLASH_WORDS * 4)      // 100352

#define FLASH_ISSUE_KV(s_, t0_) {                                              \
    unsigned* st_ = ringg + (s_) * 4096;                                       \
    _Pragma("unroll") for (int j_ = 0; j_ < 4; j_++) {                         \
        const int c_ = tidg + j_ * 128;                                        \
        const int dp_ = c_ >> 7, tc_ = (c_ >> 2) & 31, w4_ = (c_ & 3) * 4;     \
        cp16(st_ + dp_ * 512 + tc_ * 16 + w4_,                                 \
             Kg + (size_t)(dp_ * 2304 + (t0_) + tc_) * 16 + w4_);              \
    }                                                                          \
    _Pragma("unroll") for (int j_ = 0; j_ < 4; j_++) {                         \
        const int c_ = tidg + j_ * 128;                                        \
        cp16(st_ + 2048 + c_ * 4, Vg + (size_t)((t0_) >> 4) * 1024 + c_ * 4);  \
    }                                                                          \
    cpcommit(); }

__global__ __launch_bounds__(256, 2) void flash_attn()
{
    extern __shared__ unsigned smw[];
    unsigned* QP = smw;   // Q staging, later per-group P

    const int tid  = threadIdx.x;
    const int warp = tid >> 5, lane = tid & 31;
    const int q = lane & 3, r = lane >> 2;
    const int g    = warp >> 2;
    const int tidg = tid & 127;
    const int rw   = warp * 16;
    const int rwl  = (warp & 3) * 16;
    unsigned* Pg   = QP + g * 2304;
    unsigned* ringg = smw + OFF_R + g * 8192;
    const int bh = blockIdx.y;
    const int s0 = blockIdx.x * 128;

    const unsigned* Qg = g_Q + (size_t)bh * 147456;
    const unsigned* Kg = g_K + (size_t)bh * 147456;
    const unsigned* Vg = g_V + (size_t)bh * 147456;

#pragma unroll
    for (int j = 0; j < 8; j++) {
        const int c = tid * 8 + j;
        const int dd = c >> 5, sc = (c & 31) * 4;
        cp16(QP + dd * QLD + sc, Qg + (size_t)dd * SEQ + s0 + sc);
    }
    cpcommit();
    FLASH_ISSUE_KV(0, 0)
    cpwait<1>();
    __syncthreads();

    unsigned qa[8][4];
#pragma unroll
    for (int ks = 0; ks < 8; ks++) {
        qa[ks][0] = QP[(ks * 8 + q) * QLD + rw + r];
        qa[ks][1] = QP[(ks * 8 + q) * QLD + rw + r + 8];
        qa[ks][2] = QP[(ks * 8 + q + 4) * QLD + rw + r];
        qa[ks][3] = QP[(ks * 8 + q + 4) * QLD + rw + r + 8];
    }
    __syncthreads();

    float O[8][4];
#pragma unroll
    for (int i = 0; i < 8; i++)
#pragma unroll
        for (int j = 0; j < 4; j++) O[i][j] = 0.0f;

    float mA = -1e30f, mB = -1e30f, lA = 0.0f, lB = 0.0f;

    for (int it = 0; it < 72; it++) {
        cpwait<0>();
        asm volatile("bar.sync %0, 128;" :: "r"(g + 1) : "memory");
        if (it < 71) FLASH_ISSUE_KV((it + 1) & 1, (it + 1) * 32)
        unsigned* Ks = ringg + (it & 1) * 4096;
        unsigned* Vs = Ks + 2048;

        float S[4][4];
#pragma unroll
        for (int tn = 0; tn < 4; tn++)
#pragma unroll
            for (int j = 0; j < 4; j++) S[tn][j] = 0.0f;

#pragma unroll
        for (int dp = 0; dp < 4; dp++)
#pragma unroll
            for (int tn = 0; tn < 4; tn++) {
                const uint4 kb = *(const uint4*)&Ks[dp * 512 +
                                                    (tn * 8 + r) * 16 + q * 4];
                mma_tf32(S[tn], qa[2 * dp],     kb.x, kb.y);
                mma_tf32(S[tn], qa[2 * dp + 1], kb.z, kb.w);
            }

        float mxA = -1e30f, mxB = -1e30f;
#pragma unroll
        for (int tn = 0; tn < 4; tn++) {
            mxA = fmaxf(mxA, fmaxf(S[tn][0], S[tn][1]));
            mxB = fmaxf(mxB, fmaxf(S[tn][2], S[tn][3]));
        }
        mxA = fmaxf(mxA, __shfl_xor_sync(0xffffffffu, mxA, 1));
        mxA = fmaxf(mxA, __shfl_xor_sync(0xffffffffu, mxA, 2));
        mxB = fmaxf(mxB, __shfl_xor_sync(0xffffffffu, mxB, 1));
        mxB = fmaxf(mxB, __shfl_xor_sync(0xffffffffu, mxB, 2));

        const float mnA = fmaxf(mA, mxA), mnB = fmaxf(mB, mxB);
        const float cA = __expf(mA - mnA), cB = __expf(mB - mnB);
        float sA = 0.0f, sB = 0.0f;
#pragma unroll
        for (int tn = 0; tn < 4; tn++) {
            S[tn][0] = __expf(S[tn][0] - mnA); sA += S[tn][0];
            S[tn][1] = __expf(S[tn][1] - mnA); sA += S[tn][1];
            S[tn][2] = __expf(S[tn][2] - mnB); sB += S[tn][2];
            S[tn][3] = __expf(S[tn][3] - mnB); sB += S[tn][3];
        }
        sA += __shfl_xor_sync(0xffffffffu, sA, 1);
        sA += __shfl_xor_sync(0xffffffffu, sA, 2);
        sB += __shfl_xor_sync(0xffffffffu, sB, 1);
        sB += __shfl_xor_sync(0xffffffffu, sB, 2);

        lA = lA * cA + sA;  lB = lB * cB + sB;
        mA = mnA;           mB = mnB;
#pragma unroll
        for (int to = 0; to < 8; to++) {
            O[to][0] *= cA; O[to][1] *= cA;
            O[to][2] *= cB; O[to][3] *= cB;
        }

#pragma unroll
        for (int tn = 0; tn < 4; tn++) {
            const int t = tn * 8 + 2 * q;
            *(uint2*)&Pg[(rwl + r) * PST + t] =
                make_uint2(f2tf(S[tn][0]), f2tf(S[tn][1]));
            *(uint2*)&Pg[(rwl + r + 8) * PST + t] =
                make_uint2(f2tf(S[tn][2]), f2tf(S[tn][3]));
        }
        __syncwarp();

#pragma unroll
        for (int tp = 0; tp < 2; tp++) {
            const int k0 = tp * 16;
            unsigned ae[4], ao[4];
            ae[0] = Pg[(rwl + r) * PST + k0 + q];
            ae[1] = Pg[(rwl + r + 8) * PST + k0 + q];
            ae[2] = Pg[(rwl + r) * PST + k0 + q + 4];
            ae[3] = Pg[(rwl + r + 8) * PST + k0 + q + 4];
            ao[0] = Pg[(rwl + r) * PST + k0 + 8 + q];
            ao[1] = Pg[(rwl + r + 8) * PST + k0 + 8 + q];
            ao[2] = Pg[(rwl + r) * PST + k0 + 8 + q + 4];
            ao[3] = Pg[(rwl + r + 8) * PST + k0 + 8 + q + 4];
#pragma unroll
            for (int to = 0; to < 8; to++) {
                const uint4 vb = *(const uint4*)&Vs[tp * 1024 +
                                                    (to * 8 + r) * 16 + q * 4];
                mma_tf32(O[to], ae, vb.x, vb.y);
                mma_tf32(O[to], ao, vb.z, vb.w);
            }
        }
    }

    const float iA = 1.0f / lA, iB = 1.0f / lB;
    const int sA0 = s0 + rw + r, sB0 = sA0 + 8;
    const int w0 = ((2 * q) & 3) * 2 + ((2 * q) >> 2);
    const int w1 = ((2 * q + 1) & 3) * 2 + ((2 * q + 1) >> 2);
    unsigned* Og = g_O + (size_t)bh * 147456;
#pragma unroll
    for (int to = 0; to < 8; to++) {
        const size_t rowb = (size_t)to * 18432;
        Og[rowb + (size_t)sA0 * 8 + w0] = f2tf(O[to][0] * iA);
        Og[rowb + (size_t)sA0 * 8 + w1] = f2tf(O[to][1] * iA);
        Og[rowb + (size_t)sB0 * 8 + w0] = f2tf(O[to][2] * iB);
        Og[rowb + (size_t)sB0 * 8 + w1] = f2tf(O[to][3] * iB);
    }
}

// ---------------------------------------------------------------------------
extern "C" void kernel_launch(void* const* d_in, const int* in_sizes, int n_in,
                              void* d_out, int out_size)
{
    const float* x    = (const float*)d_in[0];
    const float* Wqkv = (const float*)d_in[1];
    const float* bqkv = (const float*)d_in[2];
    const float* Wout = (const float*)d_in[3];
    const float* bout = (const float*)d_in[4];
    float* out = (float*)d_out;

    cudaFuncSetAttribute(qkv_gemm,  cudaFuncAttributeMaxDynamicSharedMemorySize, PRJ_SMEM);
    cudaFuncSetAttribute(out_gemm,  cudaFuncAttributeMaxDynamicSharedMemorySize, PRJ_SMEM);
    cudaFuncSetAttribute(flash_attn, cudaFuncAttributeMaxDynamicSharedMemorySize, FLASH_BYTES);

    prep<<<1184, 256>>>(x, Wqkv, Wout);
    qkv_gemm<<<dim3(SEQ / 128, MQKV / 128, BATCH), 256, PRJ_SMEM>>>(bqkv);
    flash_attn<<<dim3(SEQ / 128, BATCH * NH), 256, FLASH_BYTES>>>();
    out_gemm<<<dim3(SEQ / 128, CDIM / 128, BATCH), 256, PRJ_SMEM>>>(bout, out);
}

// round 12
// speedup vs baseline: 7.8344x; 1.6734x over previous
#include <cuda_runtime.h>
#include <cuda_fp16.h>

// ---------------------------------------------------------------------------
// MultiHeadSelfAttention, fp16 mma.sync (m16n8k16, fp32 accum) + cp.async.
// Every 32-bit operand word = f16x2 packing the k-pair (k, k+8) of a 16-k
// slab; A and B use the same slot->k map so the hardware dot-product is
// exact under the permutation.
//   prep      : x -> f16x2 pair-interleaved; Wqkv/Wout -> A-fragment order.
//   qkv_gemm  : BK=32 (2 k16 steps), 4-stage one-barrier pipeline.
//               Q plain-ish word layout *0.125; K/V paired 16-word records.
//   flash_attn: two independent 4-warp groups, private 32-key 4-stage rings,
//               named barriers; K/V fragment pairs = single LDS.128.
//   out_gemm  : BK=32, 4-stage pipeline on f16x2 pair-interleaved O.
// ---------------------------------------------------------------------------

#define BATCH 4
#define CDIM  512
#define SEQ   2304
#define NH    8
#define HD    64
#define MQKV  1536
#define SCRH  (BATCH * CDIM * SEQ / 2)   // f16x2 words

__device__ __align__(16) unsigned g_Q[SCRH];   // [bh][dp*8+w][s], w-pair (16dp+w,+8)
__device__ __align__(16) unsigned g_K[SCRH];   // ((bh*2+dpp)*2304+t)*16 + p
__device__ __align__(16) unsigned g_V[SCRH];   // ((bh*72+tpp)*64+d)*16 + p
__device__ __align__(16) unsigned g_O[SCRH];   // ((b*32+ks)*2304+s)*8 + pw
__device__ __align__(16) unsigned g_Xt[SCRH];  // ((b*32+ks)*2304+s)*8 + pw
__device__ __align__(16) unsigned g_Wq[MQKV * CDIM / 2];  // A-fragment order
__device__ __align__(16) unsigned g_Wo[CDIM * CDIM / 2];  // A-fragment order

__device__ __forceinline__ unsigned h2(float lo, float hi) {
    __half2 t = __floats2half2_rn(lo, hi);
    return *(unsigned*)&t;
}

__device__ __forceinline__ void mma_f16(float* c, const unsigned* a,
                                        unsigned b0, unsigned b1) {
    asm volatile(
        "mma.sync.aligned.m16n8k16.row.col.f32.f16.f16.f32 "
        "{%0,%1,%2,%3}, {%4,%5,%6,%7}, {%8,%9}, {%0,%1,%2,%3};"
        : "+f"(c[0]), "+f"(c[1]), "+f"(c[2]), "+f"(c[3])
        : "r"(a[0]), "r"(a[1]), "r"(a[2]), "r"(a[3]), "r"(b0), "r"(b1));
}

__device__ __forceinline__ void cp16(unsigned* dst, const unsigned* src) {
    unsigned da = (unsigned)__cvta_generic_to_shared(dst);
    asm volatile("cp.async.cg.shared.global [%0], [%1], 16;"
                 :: "r"(da), "l"(src));
}
__device__ __forceinline__ void cpcommit() {
    asm volatile("cp.async.commit_group;");
}
template <int N> __device__ __forceinline__ void cpwait() {
    asm volatile("cp.async.wait_group %0;" :: "n"(N));
}

// ---------------------------------------------------------------------------
// prep. X word at pos pw holds x k-pair (k0+w, k0+w+8), pw(w)=(w&3)*2+(w>>2).
// W in A-fragment order: reg j of (mb,ks,g,lane):
//   m = mb*128 + g*16 + (j&1)*8 + (lane>>2)
//   klo = ks*16 + (lane&3) + (j>>1)*4 ; pair (klo, klo+8)
// ---------------------------------------------------------------------------
__global__ void prep(const float* __restrict__ x,
                     const float* __restrict__ Wqkv,
                     const float* __restrict__ Wout)
{
    const int stride = gridDim.x * blockDim.x;
    const int i0 = blockIdx.x * blockDim.x + threadIdx.x;
    for (int o = i0; o < SCRH; o += stride) {
        const int pos = o & 7;
        const int idx = o >> 3;
        const int s = idx % 2304;
        const int slab = idx / 2304;               // b*32 + ks
        const int w = (pos >> 1) + (pos & 1) * 4;
        const int b = slab >> 5;
        const int k = (slab & 31) * 16 + w;
        g_Xt[o] = h2(x[((size_t)(b * 512 + k)) * 2304 + s],
                     x[((size_t)(b * 512 + k + 8)) * 2304 + s]);
    }
    for (int o = i0; o < MQKV * CDIM / 2; o += stride) {
        const int j = o & 3, lane = (o >> 2) & 31, g = (o >> 7) & 7;
        const int ks = (o >> 10) & 31, mb = o >> 15;
        const int m = mb * 128 + g * 16 + (j & 1) * 8 + (lane >> 2);
        const int klo = ks * 16 + (lane & 3) + (j >> 1) * 4;
        g_Wq[o] = h2(Wqkv[m * CDIM + klo], Wqkv[m * CDIM + klo + 8]);
    }
    for (int o = i0; o < CDIM * CDIM / 2; o += stride) {
        const int j = o & 3, lane = (o >> 2) & 31, g = (o >> 7) & 7;
        const int ks = (o >> 10) & 31, mb = o >> 15;
        const int m = mb * 128 + g * 16 + (j & 1) * 8 + (lane >> 2);
        const int klo = ks * 16 + (lane & 3) + (j >> 1) * 4;
        g_Wo[o] = h2(Wout[m * CDIM + klo], Wout[m * CDIM + klo + 8]);
    }
}

// ---------------------------------------------------------------------------
// Projection mainloop: 128x128 tile, BK=32 (2 k16 steps), 4-stage pipeline.
// Stage = Wfrag [2 ks][8 g][128] (2048) + X [2 ks][128 n][8] (2048) = 16 KB.
// ---------------------------------------------------------------------------
#define PRJ_STG  4096
#define PRJ_SMEM (4 * PRJ_STG * 4)

#define PRJ_ISSUE(s_, ks0_) {                                                  \
    unsigned* st_ = smp + (s_) * PRJ_STG;                                      \
    const unsigned* ws_ = Wg + (ks0_) * 1024;                                  \
    cp16(st_ + tid * 8,     ws_ + tid * 8);                                    \
    cp16(st_ + tid * 8 + 4, ws_ + tid * 8 + 4);                                \
    _Pragma("unroll") for (int j_ = 0; j_ < 2; j_++) {                         \
        const int c_ = tid * 2 + j_;                                           \
        const int sl_ = c_ >> 8, n_ = (c_ & 255) >> 1, h_ = (c_ & 1) * 4;      \
        cp16(st_ + 2048 + sl_ * 1024 + n_ * 8 + h_,                            \
             Xg + ((size_t)(ks0_) + sl_) * 18432 + n_ * 8 + h_);               \
    }                                                                          \
    cpcommit(); }

#define PRJ_MAINLOOP()                                                         \
    float acc[4][4][4];                                                        \
    _Pragma("unroll") for (int i = 0; i < 4; i++)                              \
    _Pragma("unroll") for (int j = 0; j < 4; j++)                              \
    _Pragma("unroll") for (int k = 0; k < 4; k++) acc[i][j][k] = 0.0f;         \
    PRJ_ISSUE(0, 0)                                                            \
    PRJ_ISSUE(1, 2)                                                            \
    PRJ_ISSUE(2, 4)                                                            \
    for (int it = 0; it < 16; it++) {                                          \
        if (it == 15) cpwait<0>();                                             \
        else if (it == 14) cpwait<1>();                                        \
        else cpwait<2>();                                                      \
        __syncthreads();                                                       \
        if (it < 13) PRJ_ISSUE((it + 3) & 3, (it + 3) * 2)                     \
        unsigned* Ws = smp + (it & 3) * PRJ_STG;                               \
        unsigned* Xs = Ws + 2048;                                              \
        _Pragma("unroll")                                                      \
        for (int ss = 0; ss < 2; ss++) {                                       \
            uint4 afr[4];                                                      \
            _Pragma("unroll") for (int tm = 0; tm < 4; tm++)                   \
                afr[tm] = *(const uint4*)&Ws[ss * 1024 +                       \
                                             ((wm >> 4) + tm) * 128 + lane * 4];\
            uint2 bfr[4];                                                      \
            _Pragma("unroll") for (int tn = 0; tn < 4; tn++)                   \
                bfr[tn] = *(const uint2*)&Xs[ss * 1024 +                       \
                                             (wn + tn * 8 + r) * 8 + q * 2];   \
            _Pragma("unroll") for (int tm = 0; tm < 4; tm++)                   \
            _Pragma("unroll") for (int tn = 0; tn < 4; tn++)                   \
                mma_f16(acc[tm][tn], (const unsigned*)&afr[tm],                \
                        bfr[tn].x, bfr[tn].y);                                 \
        }                                                                      \
    }

// ---------------------------------------------------------------------------
__global__ __launch_bounds__(256, 2) void qkv_gemm(const float* __restrict__ bias)
{
    extern __shared__ unsigned smp[];
    const int tid = threadIdx.x;
    const int b = blockIdx.z, m0 = blockIdx.y * 128, n0 = blockIdx.x * 128;
    const int lane = tid & 31, warp = tid >> 5;
    const int q = lane & 3, r = lane >> 2;
    const int wm = (warp >> 2) * 64, wn = (warp & 3) * 32;
    const unsigned* Wg = g_Wq + (size_t)(m0 >> 7) * 32768;
    const unsigned* Xg = g_Xt + (size_t)b * 589824 + (size_t)n0 * 8;

    PRJ_MAINLOOP()

    const int which = m0 >> 9;
    if (which == 0) {
        // Q: word (bh*32 + dp*8 + r) holds d-pair (dA, dA+8), row-major in s
#pragma unroll
        for (int tm = 0; tm < 4; tm++) {
            const int mA = m0 + wm + tm * 16 + r;
            const int loc = mA & 511, h = loc >> 6, dA = loc & 63;
            const int bh = b * NH + h, dp = dA >> 4;
            const float bvA = bias[mA], bvB = bias[mA + 8];
            unsigned* row = g_Q + (size_t)(bh * 32 + dp * 8 + r) * 2304;
#pragma unroll
            for (int tn = 0; tn < 4; tn++) {
                const int n = n0 + wn + tn * 8 + 2 * q;
                uint2 v;
                v.x = h2((acc[tm][tn][0] + bvA) * 0.125f,
                         (acc[tm][tn][2] + bvB) * 0.125f);
                v.y = h2((acc[tm][tn][1] + bvA) * 0.125f,
                         (acc[tm][tn][3] + bvB) * 0.125f);
                *(uint2*)(row + n) = v;
            }
        }
    } else if (which == 1) {
        // K: ((bh*2+dpp)*2304 + t)*16 + p ; p = (r&3)*4 + (r>>2) + 2*(dp&1)
#pragma unroll
        for (int tm = 0; tm < 4; tm++) {
            const int mA = m0 + wm + tm * 16 + r;
            const int loc = mA & 511, h = loc >> 6, dA = loc & 63;
            const int bh = b * NH + h, dp = dA >> 4;
            const int p0 = (r & 3) * 4 + (r >> 2) + 2 * (dp & 1);
            const float bvA = bias[mA], bvB = bias[mA + 8];
            const size_t base = (size_t)(bh * 2 + (dp >> 1)) * 36864 + p0;
#pragma unroll
            for (int tn = 0; tn < 4; tn++) {
                const int n = n0 + wn + tn * 8 + 2 * q;
                g_K[base + (size_t)n * 16]       = h2(acc[tm][tn][0] + bvA,
                                                      acc[tm][tn][2] + bvB);
                g_K[base + (size_t)(n + 1) * 16] = h2(acc[tm][tn][1] + bvA,
                                                      acc[tm][tn][3] + bvB);
            }
        }
    } else {
        // V: ((bh*72+tpp)*64 + d)*16 + p(w=t&15, sub) ; pairs (t, t+8)
#pragma unroll
        for (int tm = 0; tm < 4; tm++) {
            const int mA = m0 + wm + tm * 16 + r;
            const int loc = mA & 511, h = loc >> 6, dA = loc & 63;
            const int bh = b * NH + h;
            const float bvA = bias[mA], bvB = bias[mA + 8];
#pragma unroll
            for (int tnp = 0; tnp < 2; tnp++) {
                const int tn = tnp * 2;
                const int t0 = n0 + wn + tn * 8 + 2 * q;
                const int sub = (t0 >> 4) & 1;
                const int p0 = ((2 * q) & 3) * 4 + ((2 * q) >> 2) + 2 * sub;
                const int p1 = ((2 * q + 1) & 3) * 4 + ((2 * q + 1) >> 2) + 2 * sub;
                const size_t blk = (size_t)(bh * 72 + (t0 >> 5)) * 1024;
                g_V[blk + dA * 16 + p0] = h2(acc[tm][tn][0] + bvA,
                                             acc[tm][tn + 1][0] + bvA);
                g_V[blk + dA * 16 + p1] = h2(acc[tm][tn][1] + bvA,
                                             acc[tm][tn + 1][1] + bvA);
                g_V[blk + (dA + 8) * 16 + p0] = h2(acc[tm][tn][2] + bvB,
                                                   acc[tm][tn + 1][2] + bvB);
                g_V[blk + (dA + 8) * 16 + p1] = h2(acc[tm][tn][3] + bvB,
                                                   acc[tm][tn + 1][3] + bvB);
            }
        }
    }
}

// ---------------------------------------------------------------------------
__global__ __launch_bounds__(256, 2) void out_gemm(const float* __restrict__ bias,
                                                   float* __restrict__ Y)
{
    extern __shared__ unsigned smp[];
    const int tid = threadIdx.x;
    const int b = blockIdx.z, m0 = blockIdx.y * 128, n0 = blockIdx.x * 128;
    const int lane = tid & 31, warp = tid >> 5;
    const int q = lane & 3, r = lane >> 2;
    const int wm = (warp >> 2) * 64, wn = (warp & 3) * 32;
    const unsigned* Wg = g_Wo + (size_t)(m0 >> 7) * 32768;
    const unsigned* Xg = g_O + (size_t)b * 589824 + (size_t)n0 * 8;

    PRJ_MAINLOOP()

#pragma unroll
    for (int tm = 0; tm < 4; tm++) {
        const int mA = m0 + wm + tm * 16 + r;
        const float bvA = bias[mA], bvB = bias[mA + 8];
        float* rowA = Y + ((size_t)b * CDIM + mA) * SEQ;
        float* rowB = Y + ((size_t)b * CDIM + mA + 8) * SEQ;
#pragma unroll
        for (int tn = 0; tn < 4; tn++) {
            const int n = n0 + wn + tn * 8 + 2 * q;
            *(float2*)(rowA + n) = make_float2(acc[tm][tn][0] + bvA,
                                               acc[tm][tn][1] + bvA);
            *(float2*)(rowB + n) = make_float2(acc[tm][tn][2] + bvB,
                                               acc[tm][tn][3] + bvB);
        }
    }
}

// ---------------------------------------------------------------------------
// flash_attn: grid (18, 32), 256 thr, 2 CTAs/SM. Two independent 4-warp
// groups, 32-key tiles, 4-stage rings (wait_group 2), named barriers.
// Smem words: QP union(Qstage[32][136]=4352 ; P: grp g at g*1280, [64][20])
//           | rings: grp g at 4352 + g*8192, stage s at +s*2048
//             (K [2 dpp][32 t][16] = 1024 | V [64 d][16] = 1024)
// ---------------------------------------------------------------------------
#define PST 20
#define OFF_R 4352
#define FLASH_WORDS (OFF_R + 2 * 8192)     // 20736
#define FLASH_BYTES (FLASH_WORDS * 4)      // 82944

#define FLASH_ISSUE_KV(s_, t0_) {                                              \
    unsigned* st_ = ringg + (s_) * 2048;                                       \
    _Pragma("unroll") for (int j_ = 0; j_ < 2; j_++) {                         \
        const int c_ = tidg * 8 + j_ * 4;                                      \
        cp16(st_ + c_, Kg + (size_t)(c_ >> 9) * 36864 +                        \
                            (size_t)(t0_) * 16 + (c_ & 511));                  \
    }                                                                          \
    _Pragma("unroll") for (int j_ = 0; j_ < 2; j_++) {                         \
        const int c_ = tidg * 8 + j_ * 4;                                      \
        cp16(st_ + 1024 + c_, Vg + (size_t)((t0_) >> 5) * 1024 + c_);          \
    }                                                                          \
    cpcommit(); }

__global__ __launch_bounds__(256, 2) void flash_attn()
{
    extern __shared__ unsigned smw[];
    unsigned* QP = smw;   // Q staging, later per-group P

    const int tid  = threadIdx.x;
    const int warp = tid >> 5, lane = tid & 31;
    const int q = lane & 3, r = lane >> 2;
    const int g    = warp >> 2;
    const int tidg = tid & 127;
    const int rw   = warp * 16;
    const int rwl  = (warp & 3) * 16;
    unsigned* Pg   = QP + g * 1280;
    unsigned* ringg = smw + OFF_R + g * 8192;
    const int bh = blockIdx.y;
    const int s0 = blockIdx.x * 128;

    const unsigned* Qg = g_Q + (size_t)bh * 73728;
    const unsigned* Kg = g_K + (size_t)bh * 73728;
    const unsigned* Vg = g_V + (size_t)bh * 73728;

    // Q stage + first three K/V tiles of this group
#pragma unroll
    for (int j = 0; j < 4; j++) {
        const int c = tid * 16 + j * 4;
        const int dw = c >> 7, sc = c & 127;
        cp16(QP + dw * 136 + sc, Qg + (size_t)dw * 2304 + s0 + sc);
    }
    cpcommit();
    FLASH_ISSUE_KV(0, 0)
    FLASH_ISSUE_KV(1, 32)
    FLASH_ISSUE_KV(2, 64)
    cpwait<3>();
    __syncthreads();

    // Q fragments to registers: qa[dp][.] covers d in [16dp, 16dp+16)
    unsigned qa[4][4];
#pragma unroll
    for (int dp = 0; dp < 4; dp++) {
        qa[dp][0] = QP[(dp * 8 + q) * 136 + rw + r];
        qa[dp][1] = QP[(dp * 8 + q) * 136 + rw + r + 8];
        qa[dp][2] = QP[(dp * 8 + q + 4) * 136 + rw + r];
        qa[dp][3] = QP[(dp * 8 + q + 4) * 136 + rw + r + 8];
    }
    __syncthreads();   // all warps done with Qstage before P overwrites it

    float O[8][4];
#pragma unroll
    for (int i = 0; i < 8; i++)
#pragma unroll
        for (int j = 0; j < 4; j++) O[i][j] = 0.0f;

    float mA = -1e30f, mB = -1e30f, lA = 0.0f, lB = 0.0f;

    for (int it = 0; it < 72; it++) {
        if (it <= 69) cpwait<2>();
        else if (it == 70) cpwait<1>();
        else cpwait<0>();
        asm volatile("bar.sync %0, 128;" :: "r"(g + 1) : "memory");
        if (it < 69) FLASH_ISSUE_KV((it + 3) & 3, (it + 3) * 32)
        unsigned* Ks = ringg + (it & 3) * 2048;
        unsigned* Vs = Ks + 1024;

        // S[16 warp rows][32 t] = Q . K  (K pair-record: one LDS.128/2 mma)
        float S[4][4];
#pragma unroll
        for (int tn = 0; tn < 4; tn++)
#pragma unroll
            for (int j = 0; j < 4; j++) S[tn][j] = 0.0f;

#pragma unroll
        for (int dpp = 0; dpp < 2; dpp++)
#pragma unroll
            for (int tn = 0; tn < 4; tn++) {
                const uint4 kb = *(const uint4*)&Ks[dpp * 512 +
                                                    (tn * 8 + r) * 16 + q * 4];
                mma_f16(S[tn], qa[2 * dpp],     kb.x, kb.y);
                mma_f16(S[tn], qa[2 * dpp + 1], kb.z, kb.w);
            }

        // online softmax (rows rw+r and rw+r+8)
        float mxA = -1e30f, mxB = -1e30f;
#pragma unroll
        for (int tn = 0; tn < 4; tn++) {
            mxA = fmaxf(mxA, fmaxf(S[tn][0], S[tn][1]));
            mxB = fmaxf(mxB, fmaxf(S[tn][2], S[tn][3]));
        }
        mxA = fmaxf(mxA, __shfl_xor_sync(0xffffffffu, mxA, 1));
        mxA = fmaxf(mxA, __shfl_xor_sync(0xffffffffu, mxA, 2));
        mxB = fmaxf(mxB, __shfl_xor_sync(0xffffffffu, mxB, 1));
        mxB = fmaxf(mxB, __shfl_xor_sync(0xffffffffu, mxB, 2));

        const float mnA = fmaxf(mA, mxA), mnB = fmaxf(mB, mxB);
        const float cA = __expf(mA - mnA), cB = __expf(mB - mnB);
        float sA = 0.0f, sB = 0.0f;
#pragma unroll
        for (int tn = 0; tn < 4; tn++) {
            S[tn][0] = __expf(S[tn][0] - mnA); sA += S[tn][0];
            S[tn][1] = __expf(S[tn][1] - mnA); sA += S[tn][1];
            S[tn][2] = __expf(S[tn][2] - mnB); sB += S[tn][2];
            S[tn][3] = __expf(S[tn][3] - mnB); sB += S[tn][3];
        }
        sA += __shfl_xor_sync(0xffffffffu, sA, 1);
        sA += __shfl_xor_sync(0xffffffffu, sA, 2);
        sB += __shfl_xor_sync(0xffffffffu, sB, 1);
        sB += __shfl_xor_sync(0xffffffffu, sB, 2);

        lA = lA * cA + sA;  lB = lB * cB + sB;
        mA = mnA;           mB = mnB;
#pragma unroll
        for (int to = 0; to < 8; to++) {
            O[to][0] *= cA; O[to][1] *= cA;
            O[to][2] *= cB; O[to][3] *= cB;
        }

        // P as f16x2 t-pairs (t, t+8): word [row][slab*8 + w]
        {
            uint2 v;
            v.x = h2(S[0][0], S[1][0]); v.y = h2(S[0][1], S[1][1]);
            *(uint2*)&Pg[(rwl + r) * PST + 2 * q] = v;
            v.x = h2(S[2][0], S[3][0]); v.y = h2(S[2][1], S[3][1]);
            *(uint2*)&Pg[(rwl + r) * PST + 8 + 2 * q] = v;
            v.x = h2(S[0][2], S[1][2]); v.y = h2(S[0][3], S[1][3]);
            *(uint2*)&Pg[(rwl + r + 8) * PST + 2 * q] = v;
            v.x = h2(S[2][2], S[3][2]); v.y = h2(S[2][3], S[3][3]);
            *(uint2*)&Pg[(rwl + r + 8) * PST + 8 + 2 * q] = v;
        }
        __syncwarp();

        // O += P . V  (V pair-record: one LDS.128 covers both k16 steps)
#pragma unroll
        for (int slab = 0; slab < 2; slab++) {
            unsigned a[4];
            a[0] = Pg[(rwl + r) * PST + slab * 8 + q];
            a[1] = Pg[(rwl + r + 8) * PST + slab * 8 + q];
            a[2] = Pg[(rwl + r) * PST + slab * 8 + q + 4];
            a[3] = Pg[(rwl + r + 8) * PST + slab * 8 + q + 4];
            if (slab == 0) {
#pragma unroll
                for (int to = 0; to < 8; to++) {
                    const uint4 vb = *(const uint4*)&Vs[(to * 8 + r) * 16 + q * 4];
                    mma_f16(O[to], a, vb.x, vb.y);
                }
            } else {
#pragma unroll
                for (int to = 0; to < 8; to++) {
                    const uint4 vb = *(const uint4*)&Vs[(to * 8 + r) * 16 + q * 4];
                    mma_f16(O[to], a, vb.z, vb.w);
                }
            }
        }
    }

    // normalize + store O as f16x2 channel-pairs for out_gemm
    const float iA = 1.0f / lA, iB = 1.0f / lB;
    const int sA0 = s0 + rw + r, sB0 = sA0 + 8;
    const int b_ = bh >> 3, h_ = bh & 7;
    const int pw0 = ((2 * q) & 3) * 2 + ((2 * q) >> 2);
    const int pw1 = ((2 * q + 1) & 3) * 2 + ((2 * q + 1) >> 2);
#pragma unroll
    for (int top = 0; top < 8; top += 2) {
        const size_t base = (size_t)(b_ * 32 + h_ * 4 + (top >> 1)) * 2304;
        g_O[(base + sA0) * 8 + pw0] = h2(O[top][0] * iA, O[top + 1][0] * iA);
        g_O[(base + sA0) * 8 + pw1] = h2(O[top][1] * iA, O[top + 1][1] * iA);
        g_O[(base + sB0) * 8 + pw0] = h2(O[top][2] * iB, O[top + 1][2] * iB);
        g_O[(base + sB0) * 8 + pw1] = h2(O[top][3] * iB, O[top + 1][3] * iB);
    }
}

// ---------------------------------------------------------------------------
extern "C" void kernel_launch(void* const* d_in, const int* in_sizes, int n_in,
                              void* d_out, int out_size)
{
    const float* x    = (const float*)d_in[0];
    const float* Wqkv = (const float*)d_in[1];
    const float* bqkv = (const float*)d_in[2];
    const float* Wout = (const float*)d_in[3];
    const float* bout = (const float*)d_in[4];
    float* out = (float*)d_out;

    cudaFuncSetAttribute(qkv_gemm,  cudaFuncAttributeMaxDynamicSharedMemorySize, PRJ_SMEM);
    cudaFuncSetAttribute(out_gemm,  cudaFuncAttributeMaxDynamicSharedMemorySize, PRJ_SMEM);
    cudaFuncSetAttribute(flash_attn, cudaFuncAttributeMaxDynamicSharedMemorySize, FLASH_BYTES);

    prep<<<1184, 256>>>(x, Wqkv, Wout);
    qkv_gemm<<<dim3(SEQ / 128, MQKV / 128, BATCH), 256, PRJ_SMEM>>>(bqkv);
    flash_attn<<<dim3(SEQ / 128, BATCH * NH), 256, FLASH_BYTES>>>();
    out_gemm<<<dim3(SEQ / 128, CDIM / 128, BATCH), 256, PRJ_SMEM>>>(bout, out);
}